// round 11
// baseline (speedup 1.0000x reference)
#include <cuda_runtime.h>
#include <cuda_bf16.h>
#include <cuda_fp16.h>
#include <math.h>
#include <stdint.h>

#define D_MODEL   1024
#define D_STATE   64
#define D_CONV    4
#define D_INNER   2048
#define NHEADS    32
#define HEADDIM   64
#define CHUNK     64
#define CONV_DIM  2176
#define D_IN_PROJ 4256
#define B_SZ      2
#define T_LEN     4096
#define M_TOK     (B_SZ * T_LEN)   // 8192
#define NCHUNK    (T_LEN / CHUNK)  // 64
#define NBH       (B_SZ * NHEADS)  // 64

// ------------------------- scratch (device globals) -------------------------
__device__ __half g_zxbcdt[(size_t)M_TOK * D_IN_PROJ];
__device__ __half g_xbc[(size_t)M_TOK * CONV_DIM];
__device__ float  g_dt[(size_t)M_TOK * NHEADS];
__device__ __half g_y[(size_t)M_TOK * D_INNER];

__device__ __half g_uh[(size_t)M_TOK * D_MODEL];
__device__ __half g_wih[(size_t)D_IN_PROJ * D_MODEL];
__device__ __half g_yh[(size_t)M_TOK * D_INNER];
__device__ __half g_woh[(size_t)D_MODEL * D_INNER];

__device__ __half g_cs[(size_t)NBH * NCHUNK * 64 * 64];
__device__ __half g_ps[(size_t)NBH * NCHUNK * 64 * 64];
__device__ float  g_T[NBH * NCHUNK];
__device__ float  g_el[(size_t)NBH * NCHUNK * CHUNK];

// ------------------------- helpers ------------------------------------------
__device__ __forceinline__ uint32_t smem_u32(const void* p) {
    uint32_t a;
    asm("{ .reg .u64 t; cvta.to.shared.u64 t, %1; cvt.u32.u64 %0, t; }"
        : "=r"(a) : "l"(p));
    return a;
}
__device__ __forceinline__ void ldsm_x4(uint32_t& r0, uint32_t& r1,
                                        uint32_t& r2, uint32_t& r3,
                                        uint32_t addr) {
    asm volatile("ldmatrix.sync.aligned.m8n8.x4.shared.b16 {%0,%1,%2,%3}, [%4];"
                 : "=r"(r0), "=r"(r1), "=r"(r2), "=r"(r3) : "r"(addr));
}
__device__ __forceinline__ void ldsm_x4_t(uint32_t& r0, uint32_t& r1,
                                          uint32_t& r2, uint32_t& r3,
                                          uint32_t addr) {
    asm volatile("ldmatrix.sync.aligned.m8n8.x4.trans.shared.b16 {%0,%1,%2,%3}, [%4];"
                 : "=r"(r0), "=r"(r1), "=r"(r2), "=r"(r3) : "r"(addr));
}
__device__ __forceinline__ void mma_fp16(float* c, const uint32_t* a,
                                         uint32_t b0, uint32_t b1) {
    asm volatile(
        "mma.sync.aligned.m16n8k16.row.col.f32.f16.f16.f32 "
        "{%0,%1,%2,%3}, {%4,%5,%6,%7}, {%8,%9}, {%0,%1,%2,%3};"
        : "+f"(c[0]), "+f"(c[1]), "+f"(c[2]), "+f"(c[3])
        : "r"(a[0]), "r"(a[1]), "r"(a[2]), "r"(a[3]), "r"(b0), "r"(b1));
}
__device__ __forceinline__ void cp16(uint32_t dst, const void* src) {
    asm volatile("cp.async.cg.shared.global [%0], [%1], 16;"
                 :: "r"(dst), "l"(src));
}
__device__ __forceinline__ void cp16z(uint32_t dst, const void* src, int valid) {
    int sz = valid ? 16 : 0;
    asm volatile("cp.async.cg.shared.global [%0], [%1], 16, %2;"
                 :: "r"(dst), "l"(src), "r"(sz));
}
#define CP_COMMIT() asm volatile("cp.async.commit_group;" ::: "memory")
#define CP_WAIT(N)  asm volatile("cp.async.wait_group %0;" :: "n"(N) : "memory")

__device__ __forceinline__ uint32_t swz(int row, int kb) {
    return (uint32_t)(row * 64 + ((((kb >> 4) ^ (row & 3)) << 4) | (kb & 15)));
}
__device__ __forceinline__ uint32_t swz128(int row, int cb) {
    return (uint32_t)(row * 128 + (cb ^ ((row & 7) << 4)));
}
__device__ __forceinline__ uint32_t packh2(float a, float b) {
    __half2 h = __floats2half2_rn(a, b);
    return *(uint32_t*)&h;
}
__device__ __forceinline__ float2 unpackh2(uint32_t w) {
    __half2 h = *(__half2*)&w;
    return make_float2(__half2float(h.x), __half2float(h.y));
}
__device__ __forceinline__ void store2(float* p, float a, float b) {
    *(float2*)p = make_float2(a, b);
}
__device__ __forceinline__ void store2(__half* p, float a, float b) {
    *(__half2*)p = __floats2half2_rn(a, b);
}

// ------------------------- fp32 -> fp16 convert -----------------------------
__global__ void cvt_kernel(const float* __restrict__ src,
                           __half* __restrict__ dst, int n) {
    int i = blockIdx.x * 256 + threadIdx.x;
    if (i * 2 < n) {
        float2 v = *(const float2*)(src + i * 2);
        *(__half2*)(dst + i * 2) = __floats2half2_rn(v.x, v.y);
    }
}

// ------------------------- narrow HMMA GEMM: 128x128x32, 2 CTA/SM -----------
#define TILE_B   8192
#define STAGE_B  (2 * TILE_B)
#define NSTAGE   4
#define GEMM_SMEM (NSTAGE * STAGE_B)   // 64 KB
template <typename OT>
__global__ void __launch_bounds__(256) gemm_mma_kernel(
    const __half* __restrict__ A, const __half* __restrict__ B,
    OT* __restrict__ C, int M, int N, int K) {
    extern __shared__ char smem[];
    const uint32_t sb = smem_u32(smem);

    const int tid  = threadIdx.x;
    const int wid  = tid >> 5;
    const int lane = tid & 31;
    const int m0 = blockIdx.y << 7;
    const int n0 = blockIdx.x << 7;
    const int wm0 = (wid >> 2) << 6;
    const int wn0 = (wid & 3) << 5;

    const int r0c = tid >> 2, c0c = tid & 3;
    const int r1c = (tid + 256) >> 2, c1c = tid & 3;

    float acc[4][4][4];
#pragma unroll
    for (int f = 0; f < 4; f++)
#pragma unroll
        for (int g = 0; g < 4; g++)
#pragma unroll
            for (int e = 0; e < 4; e++) acc[f][g][e] = 0.f;

    const int nk = K >> 5;

    auto load_stage = [&](int kc, int s) {
        const int k0 = kc << 5;
        const uint32_t st = sb + s * STAGE_B;
        {
            const size_t o0 = (size_t)(m0 + r0c) * K + k0 + c0c * 8;
            const size_t o1 = (size_t)(m0 + r1c) * K + k0 + c1c * 8;
            cp16(st + swz(r0c, c0c * 16), A + o0);
            cp16(st + swz(r1c, c1c * 16), A + o1);
        }
        {
            const int v0 = (n0 + r0c) < N, v1 = (n0 + r1c) < N;
            const size_t o0 = v0 ? (size_t)(n0 + r0c) * K + k0 + c0c * 8 : 0;
            const size_t o1 = v1 ? (size_t)(n0 + r1c) * K + k0 + c1c * 8 : 0;
            cp16z(st + TILE_B + swz(r0c, c0c * 16), B + o0, v0);
            cp16z(st + TILE_B + swz(r1c, c1c * 16), B + o1, v1);
        }
        CP_COMMIT();
    };

    load_stage(0, 0);
    load_stage(1, 1);
    load_stage(2, 2);

    const int a_row = lane & 15;
    const int a_kb  = (lane >> 4) << 4;
    const int b_row = (lane & 7) + ((lane >> 4) << 3);
    const int b_kb  = ((lane >> 3) & 1) << 4;

    for (int kc = 0; kc < nk; kc++) {
        CP_WAIT(2);
        __syncthreads();
        if (kc + 3 < nk) load_stage(kc + 3, (kc + 3) & 3);
        else CP_COMMIT();

        const uint32_t st = sb + (kc & 3) * STAGE_B;
        const uint32_t sA = st, sB = st + TILE_B;

#pragma unroll
        for (int kk = 0; kk < 2; kk++) {
            const int kb_a = kk * 32 + a_kb;
            const int kb_b = kk * 32 + b_kb;
            uint32_t ah[4][4], bh[2][4];
#pragma unroll
            for (int f = 0; f < 4; f++) {
                const int row = wm0 + f * 16 + a_row;
                ldsm_x4(ah[f][0], ah[f][1], ah[f][2], ah[f][3],
                        sA + swz(row, kb_a));
            }
#pragma unroll
            for (int g2 = 0; g2 < 2; g2++) {
                const int row = wn0 + g2 * 16 + b_row;
                ldsm_x4(bh[g2][0], bh[g2][1], bh[g2][2], bh[g2][3],
                        sB + swz(row, kb_b));
            }
#pragma unroll
            for (int f = 0; f < 4; f++)
#pragma unroll
                for (int g = 0; g < 4; g++) {
                    const uint32_t* bf = &bh[g >> 1][(g & 1) << 1];
                    mma_fp16(acc[f][g], ah[f], bf[0], bf[1]);
                }
        }
    }

    const int er = lane >> 2;
    const int ec = (lane & 3) << 1;
#pragma unroll
    for (int f = 0; f < 4; f++) {
        const int row = m0 + wm0 + f * 16 + er;
#pragma unroll
        for (int g = 0; g < 4; g++) {
            const int col = n0 + wn0 + g * 8 + ec;
            if (col < N) {
                store2(&C[(size_t)row * N + col], acc[f][g][0], acc[f][g][1]);
                store2(&C[(size_t)(row + 8) * N + col], acc[f][g][2],
                       acc[f][g][3]);
            }
        }
    }
}

// ------------------------- wide HMMA GEMM: 128x256x32, 1 CTA/SM -------------
// warp tile 64x64 -> half the smem-read pressure per mma. Used for GEMM1 only
// (its grid is 17x64 = 1088 CTAs -> no wave-tail problem).
#define WA_TILE_B 8192                    // 128 x 32 halves
#define WB_TILE_B 16384                   // 256 x 32 halves
#define WSTAGE_B  (WA_TILE_B + WB_TILE_B) // 24576
#define WGEMM_SMEM (4 * WSTAGE_B)         // 96 KB
__global__ void __launch_bounds__(256, 1) gemm_wide_kernel(
    const __half* __restrict__ A, const __half* __restrict__ B,
    __half* __restrict__ C, int M, int N, int K) {
    extern __shared__ char smem[];
    const uint32_t sb = smem_u32(smem);

    const int tid  = threadIdx.x;
    const int wid  = tid >> 5;
    const int lane = tid & 31;
    const int m0 = blockIdx.y << 7;
    const int n0 = blockIdx.x << 8;
    const int wm0 = (wid >> 2) << 6;    // 0 or 64
    const int wn0 = (wid & 3) << 6;     // 0,64,128,192

    float acc[4][8][4];
#pragma unroll
    for (int f = 0; f < 4; f++)
#pragma unroll
        for (int g = 0; g < 8; g++)
#pragma unroll
            for (int e = 0; e < 4; e++) acc[f][g][e] = 0.f;

    const int nk = K >> 5;

    auto load_stage = [&](int kc, int s) {
        const int k0 = kc << 5;
        const uint32_t st = sb + s * WSTAGE_B;
#pragma unroll
        for (int i = 0; i < 2; i++) {
            const int q = tid + (i << 8);
            const int r = q >> 2, cc = q & 3;
            cp16(st + swz(r, cc * 16),
                 A + (size_t)(m0 + r) * K + k0 + cc * 8);
        }
#pragma unroll
        for (int i = 0; i < 4; i++) {
            const int q = tid + (i << 8);
            const int r = q >> 2, cc = q & 3;
            const int v = (n0 + r) < N;
            const size_t o = v ? (size_t)(n0 + r) * K + k0 + cc * 8 : 0;
            cp16z(st + WA_TILE_B + swz(r, cc * 16), B + o, v);
        }
        CP_COMMIT();
    };

    load_stage(0, 0);
    load_stage(1, 1);
    load_stage(2, 2);

    const int a_row = lane & 15;
    const int a_kb  = (lane >> 4) << 4;
    const int b_row = (lane & 7) + ((lane >> 4) << 3);
    const int b_kb  = ((lane >> 3) & 1) << 4;

    for (int kc = 0; kc < nk; kc++) {
        CP_WAIT(2);
        __syncthreads();
        if (kc + 3 < nk) load_stage(kc + 3, (kc + 3) & 3);
        else CP_COMMIT();

        const uint32_t st = sb + (kc & 3) * WSTAGE_B;
        const uint32_t sA = st, sB = st + WA_TILE_B;

#pragma unroll
        for (int kk = 0; kk < 2; kk++) {
            const int kb_a = kk * 32 + a_kb;
            const int kb_b = kk * 32 + b_kb;
            uint32_t ah[4][4], bh[4][4];
#pragma unroll
            for (int f = 0; f < 4; f++) {
                const int row = wm0 + f * 16 + a_row;
                ldsm_x4(ah[f][0], ah[f][1], ah[f][2], ah[f][3],
                        sA + swz(row, kb_a));
            }
#pragma unroll
            for (int g2 = 0; g2 < 4; g2++) {
                const int row = wn0 + g2 * 16 + b_row;
                ldsm_x4(bh[g2][0], bh[g2][1], bh[g2][2], bh[g2][3],
                        sB + swz(row, kb_b));
            }
#pragma unroll
            for (int f = 0; f < 4; f++)
#pragma unroll
                for (int g = 0; g < 8; g++) {
                    const uint32_t* bf = &bh[g >> 1][(g & 1) << 1];
                    mma_fp16(acc[f][g], ah[f], bf[0], bf[1]);
                }
        }
    }

    const int er = lane >> 2;
    const int ec = (lane & 3) << 1;
#pragma unroll
    for (int f = 0; f < 4; f++) {
        const int row = m0 + wm0 + f * 16 + er;
#pragma unroll
        for (int g = 0; g < 8; g++) {
            const int col = n0 + wn0 + g * 8 + ec;
            if (col < N) {
                store2(&C[(size_t)row * N + col], acc[f][g][0], acc[f][g][1]);
                store2(&C[(size_t)(row + 8) * N + col], acc[f][g][2],
                       acc[f][g][3]);
            }
        }
    }
}

// ------------------------- dt = softplus(raw + bias) ------------------------
__global__ void dt_kernel(const float* __restrict__ dt_bias) {
    const int idx = blockIdx.x * 256 + threadIdx.x;
    const int m = idx >> 5;
    const int h = idx & 31;
    float v = __half2float(
                  g_zxbcdt[(size_t)m * D_IN_PROJ + (D_INNER + CONV_DIM) + h]) +
              dt_bias[h];
    g_dt[idx] = (v > 20.f) ? v : log1pf(expf(v));
}

// ------------------------- tiled depthwise conv + SiLU (vectorized) ---------
__global__ void __launch_bounds__(256) conv_silu_kernel(
    const float* __restrict__ w, const float* __restrict__ bias) {
    __shared__ float sx[67][128];
    const int cb = blockIdx.x;
    const int tb = blockIdx.y;
    const int tid = threadIdx.x;
    const int m0 = tb * 64;
    const int zero_head = ((m0 & (T_LEN - 1)) == 0);

    for (int idx = tid; idx < 67 * 16; idx += 256) {
        const int r = idx >> 4, j = idx & 15;
        float4 z = make_float4(0.f, 0.f, 0.f, 0.f);
        uint4 raw = *(const uint4*)&z;
        if (r >= 3 || !zero_head)
            raw = *(const uint4*)&g_zxbcdt[(size_t)(m0 - 3 + r) * D_IN_PROJ +
                                           D_INNER + cb * 128 + j * 8];
        const __half2* hp = (const __half2*)&raw;
#pragma unroll
        for (int q = 0; q < 4; q++) {
            float2 v = unpackh2(((const uint32_t*)hp)[q]);
            sx[r][j * 8 + q * 2]     = v.x;
            sx[r][j * 8 + q * 2 + 1] = v.y;
        }
    }
    __syncthreads();

    const int ch = tid & 127;
    const int th = (tid >> 7) * 32;
    const int gc = cb * 128 + ch;
    const float w0 = w[gc * 4 + 0], w1 = w[gc * 4 + 1];
    const float w2 = w[gc * 4 + 2], w3 = w[gc * 4 + 3];
    const float bz = bias[gc];
#pragma unroll 8
    for (int i = 0; i < 32; i++) {
        const int t = th + i;
        float acc = bz + w0 * sx[t][ch] + w1 * sx[t + 1][ch] +
                    w2 * sx[t + 2][ch] + w3 * sx[t + 3][ch];
        g_xbc[(size_t)(m0 + t) * CONV_DIM + gc] =
            __float2half_rn(acc / (1.f + expf(-acc)));
    }
}

// ------------------------- SSD phase 1 (fp16 tensor cores) ------------------
#define OFF_X 0
#define OFF_B 8192
#define OFF_C 16384
#define OFF_M 24576
__global__ void __launch_bounds__(256) ssd1_tc(const float* __restrict__ A_log,
                                               const float* __restrict__ Dvec) {
    __shared__ __align__(16) char sm[32768];
    __shared__ float s_cum[64], s_dt[64], s_coef[64];
    const uint32_t sb = smem_u32(sm);

    const int blk = blockIdx.x;
    const int c   = blk & (NCHUNK - 1);
    const int bh  = blk >> 6;
    const int b = bh >> 5, h = bh & 31;
    const int tid = threadIdx.x, wid = tid >> 5, lane = tid & 31;
    const int r0 = (wid & 3) * 16, c0 = (wid >> 2) * 32;
    const int m0 = b * T_LEN + c * CHUNK;
    const float Ahc = -expf(A_log[h]);
    const float Dh  = Dvec[h];

#pragma unroll
    for (int i = 0; i < 6; i++) {
        int flat = tid + (i << 8);
        int t3 = flat >> 9;
        int wt = flat & 511;
        int l = wt >> 3, j = wt & 7;
        int off = (t3 == 0) ? h * HEADDIM : (t3 == 1) ? D_INNER
                                                      : D_INNER + D_STATE;
        cp16(sb + t3 * 8192 + swz128(l, j * 16),
             g_xbc + (size_t)(m0 + l) * CONV_DIM + off + j * 8);
    }
    CP_COMMIT();
    if (tid < 64) s_dt[tid] = g_dt[(size_t)(m0 + tid) * NHEADS + h];
    CP_WAIT(0);
    __syncthreads();
    if (wid == 0) {
        float v0 = Ahc * s_dt[lane * 2], v1 = Ahc * s_dt[lane * 2 + 1];
        float s = v0 + v1;
#pragma unroll
        for (int o = 1; o < 32; o <<= 1) {
            float t = __shfl_up_sync(0xFFFFFFFF, s, o);
            if (lane >= o) s += t;
        }
        float excl = s - (v0 + v1);
        s_cum[lane * 2] = excl + v0;
        s_cum[lane * 2 + 1] = excl + v0 + v1;
    }
    __syncthreads();
    if (tid < 64) {
        s_coef[tid] = s_dt[tid] * __expf(s_cum[63] - s_cum[tid]);
        g_el[(size_t)blk * 64 + tid] = __expf(s_cum[tid]);
    }
    if (tid == 0) g_T[blk] = __expf(s_cum[63]);
    __syncthreads();

    const int er = lane >> 2, ec = (lane & 3) << 1;

    // ---- step A: G = C @ B^T, mask/decay -> M (fp16) ----
    {
        float acc[4][4];
#pragma unroll
        for (int g = 0; g < 4; g++)
#pragma unroll
            for (int e = 0; e < 4; e++) acc[g][e] = 0.f;
#pragma unroll
        for (int k16 = 0; k16 < 4; k16++) {
            uint32_t ah[4];
            uint32_t aoff = swz128(r0 + (lane & 15),
                                   k16 * 32 + ((lane >> 4) << 4));
            ldsm_x4(ah[0], ah[1], ah[2], ah[3], sb + OFF_C + aoff);
            uint32_t bhf[2][4];
#pragma unroll
            for (int g2 = 0; g2 < 2; g2++) {
                uint32_t boff =
                    swz128(c0 + g2 * 16 + (lane & 7) + ((lane >> 4) << 3),
                           k16 * 32 + (((lane >> 3) & 1) << 4));
                ldsm_x4(bhf[g2][0], bhf[g2][1], bhf[g2][2], bhf[g2][3],
                        sb + OFF_B + boff);
            }
#pragma unroll
            for (int g = 0; g < 4; g++) {
                const uint32_t* bf = &bhf[g >> 1][(g & 1) << 1];
                mma_fp16(acc[g], ah, bf[0], bf[1]);
            }
        }
#pragma unroll
        for (int g = 0; g < 4; g++) {
            int s0 = c0 + g * 8 + ec;
            float cs0 = s_cum[s0], cs1 = s_cum[s0 + 1];
            float d0 = s_dt[s0], d1 = s_dt[s0 + 1];
#pragma unroll
            for (int hf = 0; hf < 2; hf++) {
                int l = r0 + er + hf * 8;
                float cl = s_cum[l];
                float v0 = (s0     <= l) ? acc[g][hf * 2 + 0] * __expf(cl - cs0) * d0 : 0.f;
                float v1 = (s0 + 1 <= l) ? acc[g][hf * 2 + 1] * __expf(cl - cs1) * d1 : 0.f;
                *(uint32_t*)(sm + OFF_M + swz128(l, s0 * 2)) = packh2(v0, v1);
            }
        }
    }
    __syncthreads();

    // ---- CX = coef(l) * x (overwrites C tile) ----
#pragma unroll
    for (int i = 0; i < 8; i++) {
        int flat = tid + (i << 8);
        int l = flat >> 5, q2 = flat & 31;
        uint32_t so = swz128(l, q2 * 4);
        float2 v = unpackh2(*(uint32_t*)(sm + OFF_X + so));
        float cf = s_coef[l];
        *(uint32_t*)(sm + OFF_C + so) = packh2(v.x * cf, v.y * cf);
    }

    // ---- step B: Y = M @ x (+ D skip) -> fp16 g_y ----
    {
        float acc[4][4];
#pragma unroll
        for (int g = 0; g < 4; g++)
#pragma unroll
            for (int e = 0; e < 4; e++) acc[g][e] = 0.f;
#pragma unroll
        for (int k16 = 0; k16 < 4; k16++) {
            uint32_t ah[4];
            uint32_t aoff = swz128(r0 + (lane & 15),
                                   k16 * 32 + ((lane >> 4) << 4));
            ldsm_x4(ah[0], ah[1], ah[2], ah[3], sb + OFF_M + aoff);
            uint32_t bhf[2][4];
#pragma unroll
            for (int g2 = 0; g2 < 2; g2++) {
                uint32_t boff =
                    swz128(k16 * 16 + ((lane >> 3) & 1) * 8 + (lane & 7),
                           (c0 + g2 * 16) * 2 + (((lane >> 4) & 1) << 4));
                ldsm_x4_t(bhf[g2][0], bhf[g2][1], bhf[g2][2], bhf[g2][3],
                          sb + OFF_X + boff);
            }
#pragma unroll
            for (int g = 0; g < 4; g++) {
                const uint32_t* bf = &bhf[g >> 1][(g & 1) << 1];
                mma_fp16(acc[g], ah, bf[0], bf[1]);
            }
        }
#pragma unroll
        for (int g = 0; g < 4; g++) {
            int p0 = c0 + g * 8 + ec;
#pragma unroll
            for (int hf = 0; hf < 2; hf++) {
                int l = r0 + er + hf * 8;
                float2 xv = unpackh2(*(uint32_t*)(sm + OFF_X + swz128(l, p0 * 2)));
                *(uint32_t*)&g_y[(size_t)(m0 + l) * D_INNER + h * HEADDIM + p0] =
                    packh2(acc[g][hf * 2 + 0] + Dh * xv.x,
                           acc[g][hf * 2 + 1] + Dh * xv.y);
            }
        }
    }
    __syncthreads();

    // ---- step C: S(p,n) = CX^T @ B -> fp16 g_cs ----
    {
        float acc[4][4];
#pragma unroll
        for (int g = 0; g < 4; g++)
#pragma unroll
            for (int e = 0; e < 4; e++) acc[g][e] = 0.f;
#pragma unroll
        for (int k16 = 0; k16 < 4; k16++) {
            uint32_t ah[4];
            uint32_t aoff =
                swz128(k16 * 16 + ((lane >> 4) & 1) * 8 + (lane & 7),
                       r0 * 2 + (((lane >> 3) & 1) << 4));
            ldsm_x4_t(ah[0], ah[1], ah[2], ah[3], sb + OFF_C + aoff);
            uint32_t bhf[2][4];
#pragma unroll
            for (int g2 = 0; g2 < 2; g2++) {
                uint32_t boff =
                    swz128(k16 * 16 + ((lane >> 3) & 1) * 8 + (lane & 7),
                           (c0 + g2 * 16) * 2 + (((lane >> 4) & 1) << 4));
                ldsm_x4_t(bhf[g2][0], bhf[g2][1], bhf[g2][2], bhf[g2][3],
                          sb + OFF_B + boff);
            }
#pragma unroll
            for (int g = 0; g < 4; g++) {
                const uint32_t* bf = &bhf[g >> 1][(g & 1) << 1];
                mma_fp16(acc[g], ah, bf[0], bf[1]);
            }
        }
        const size_t sbase = (size_t)blk * 4096;
#pragma unroll
        for (int g = 0; g < 4; g++) {
            int n0 = c0 + g * 8 + ec;
#pragma unroll
            for (int hf = 0; hf < 2; hf++) {
                int p = r0 + er + hf * 8;
                *(uint32_t*)&g_cs[sbase + p * 64 + n0] =
                    packh2(acc[g][hf * 2 + 0], acc[g][hf * 2 + 1]);
            }
        }
    }
}

// ------------------------- SSD phase 2: scan (4x par, prefetched, uint2) ----
__global__ void __launch_bounds__(256) ssd_phase2() {
    __shared__ float sT[NCHUNK];
    const int slice = blockIdx.x & 3;
    const int bh    = blockIdx.x >> 2;
    const int tid   = threadIdx.x;
    if (tid < NCHUNK) sT[tid] = g_T[bh * NCHUNK + tid];
    __syncthreads();

    const int off = slice * 1024 + tid * 4;
    const size_t b0 = (size_t)bh * NCHUNK * 4096 + off;
    float s0 = 0.f, s1 = 0.f, s2 = 0.f, s3 = 0.f;
    uint2 nxt = *(const uint2*)&g_cs[b0];
#pragma unroll 4
    for (int c = 0; c < NCHUNK; c++) {
        const size_t base = b0 + (size_t)c * 4096;
        uint2 st;
        st.x = packh2(s0, s1);
        st.y = packh2(s2, s3);
        *(uint2*)&g_ps[base] = st;
        const uint2 cur = nxt;
        if (c + 1 < NCHUNK) nxt = *(const uint2*)&g_cs[base + 4096];
        const float T = sT[c];
        float2 v0 = unpackh2(cur.x);
        float2 v1 = unpackh2(cur.y);
        s0 = s0 * T + v0.x;
        s1 = s1 * T + v0.y;
        s2 = s2 * T + v1.x;
        s3 = s3 * T + v1.y;
    }
}

// ------------------------- SSD phase 3 (fp16 tensor cores) ------------------
__global__ void __launch_bounds__(256) ssd3_tc() {
    __shared__ __align__(16) char t_C[8192];
    __shared__ __align__(16) char t_S[8192];
    __shared__ float s_el[64];
    const uint32_t aC = smem_u32(t_C), aS = smem_u32(t_S);

    const int blk = blockIdx.x;
    const int c   = blk & (NCHUNK - 1);
    const int bh  = blk >> 6;
    const int b = bh >> 5, h = bh & 31;
    const int tid = threadIdx.x, wid = tid >> 5, lane = tid & 31;
    const int r0 = (wid & 3) * 16, c0 = (wid >> 2) * 32;
    const int m0 = b * T_LEN + c * CHUNK;

#pragma unroll
    for (int i = 0; i < 2; i++) {
        int flat = tid + (i << 8);
        int l = flat >> 3, j = flat & 7;
        cp16(aC + swz128(l, j * 16),
             g_xbc + (size_t)(m0 + l) * CONV_DIM + D_INNER + D_STATE + j * 8);
        cp16(aS + swz128(l, j * 16),
             g_ps + (size_t)blk * 4096 + l * 64 + j * 8);
    }
    CP_COMMIT();
    if (tid < 64) s_el[tid] = g_el[(size_t)blk * 64 + tid];
    CP_WAIT(0);
    __syncthreads();

    float acc[4][4];
#pragma unroll
    for (int g = 0; g < 4; g++)
#pragma unroll
        for (int e = 0; e < 4; e++) acc[g][e] = 0.f;
#pragma unroll
    for (int k16 = 0; k16 < 4; k16++) {
        uint32_t ah[4];
        uint32_t aoff = swz128(r0 + (lane & 15), k16 * 32 + ((lane >> 4) << 4));
        ldsm_x4(ah[0], ah[1], ah[2], ah[3], aC + aoff);
        uint32_t bhf[2][4];
#pragma unroll
        for (int g2 = 0; g2 < 2; g2++) {
            uint32_t boff =
                swz128(c0 + g2 * 16 + (lane & 7) + ((lane >> 4) << 3),
                       k16 * 32 + (((lane >> 3) & 1) << 4));
            ldsm_x4(bhf[g2][0], bhf[g2][1], bhf[g2][2], bhf[g2][3], aS + boff);
        }
#pragma unroll
        for (int g = 0; g < 4; g++) {
            const uint32_t* bf = &bhf[g >> 1][(g & 1) << 1];
            mma_fp16(acc[g], ah, bf[0], bf[1]);
        }
    }
    const int er = lane >> 2, ec = (lane & 3) << 1;
#pragma unroll
    for (int g = 0; g < 4; g++) {
        int p0 = c0 + g * 8 + ec;
#pragma unroll
        for (int hf = 0; hf < 2; hf++) {
            int l = r0 + er + hf * 8;
            float el = s_el[l];
            uint32_t* yp =
                (uint32_t*)&g_y[(size_t)(m0 + l) * D_INNER + h * HEADDIM + p0];
            float2 cur = unpackh2(*yp);
            *yp = packh2(cur.x + el * acc[g][hf * 2 + 0],
                         cur.y + el * acc[g][hf * 2 + 1]);
        }
    }
}

// ------------------------- gate + RMSNorm -> fp16 (vectorized) --------------
__global__ void gate_rms_kernel(const float* __restrict__ norm_w,
                                __half* __restrict__ yh) {
    const int m = blockIdx.x;
    const int tid = threadIdx.x;
    const size_t ybase = (size_t)m * D_INNER;
    const size_t zbase = (size_t)m * D_IN_PROJ;
    const int i0 = tid * 8;

    uint4 yraw = *(const uint4*)&g_y[ybase + i0];
    uint4 zraw = *(const uint4*)&g_zxbcdt[zbase + i0];
    float vals[8];
    float ssum = 0.f;
    const uint32_t* yw = (const uint32_t*)&yraw;
    const uint32_t* zw = (const uint32_t*)&zraw;
#pragma unroll
    for (int q = 0; q < 4; q++) {
        float2 yv = unpackh2(yw[q]);
        float2 zv = unpackh2(zw[q]);
        float g0 = yv.x * zv.x / (1.f + expf(-zv.x));
        float g1 = yv.y * zv.y / (1.f + expf(-zv.y));
        vals[q * 2] = g0;
        vals[q * 2 + 1] = g1;
        ssum += g0 * g0 + g1 * g1;
    }
    __shared__ float red[256];
    red[tid] = ssum;
    __syncthreads();
    for (int s = 128; s > 0; s >>= 1) {
        if (tid < s) red[tid] += red[tid + s];
        __syncthreads();
    }
    const float scale = rsqrtf(red[0] / (float)D_INNER + 1e-5f);

    float4 w0 = *(const float4*)&norm_w[i0];
    float4 w1 = *(const float4*)&norm_w[i0 + 4];
    uint4 outw;
    uint32_t* ow = (uint32_t*)&outw;
    ow[0] = packh2(vals[0] * scale * w0.x, vals[1] * scale * w0.y);
    ow[1] = packh2(vals[2] * scale * w0.z, vals[3] * scale * w0.w);
    ow[2] = packh2(vals[4] * scale * w1.x, vals[5] * scale * w1.y);
    ow[3] = packh2(vals[6] * scale * w1.z, vals[7] * scale * w1.w);
    *(uint4*)&yh[ybase + i0] = outw;
}

// ---------------------------------------------------------------------------
extern "C" void kernel_launch(void* const* d_in, const int* in_sizes, int n_in,
                              void* d_out, int out_size) {
    const float* u       = (const float*)d_in[0];
    const float* W_in    = (const float*)d_in[1];
    const float* conv_w  = (const float*)d_in[2];
    const float* conv_b  = (const float*)d_in[3];
    const float* dt_bias = (const float*)d_in[4];
    const float* A_log   = (const float*)d_in[5];
    const float* Dv      = (const float*)d_in[6];
    const float* norm_w  = (const float*)d_in[7];
    const float* W_out   = (const float*)d_in[8];
    float* out = (float*)d_out;

    __half *zx_p, *uh, *wih, *yh, *woh;
    cudaGetSymbolAddress((void**)&zx_p, g_zxbcdt);
    cudaGetSymbolAddress((void**)&uh, g_uh);
    cudaGetSymbolAddress((void**)&wih, g_wih);
    cudaGetSymbolAddress((void**)&yh, g_yh);
    cudaGetSymbolAddress((void**)&woh, g_woh);

    cudaFuncSetAttribute(gemm_wide_kernel,
                         cudaFuncAttributeMaxDynamicSharedMemorySize,
                         WGEMM_SMEM);
    cudaFuncSetAttribute(gemm_mma_kernel<float>,
                         cudaFuncAttributeMaxDynamicSharedMemorySize, GEMM_SMEM);

    {
        int n = M_TOK * D_MODEL;
        cvt_kernel<<<(n / 2 + 255) / 256, 256>>>(u, uh, n);
        n = D_IN_PROJ * D_MODEL;
        cvt_kernel<<<(n / 2 + 255) / 256, 256>>>(W_in, wih, n);
        n = D_MODEL * D_INNER;
        cvt_kernel<<<(n / 2 + 255) / 256, 256>>>(W_out, woh, n);
    }

    // GEMM1: wide tile (grid 17x64, tail-free at 1 CTA/SM)
    gemm_wide_kernel
        <<<dim3((D_IN_PROJ + 255) / 256, M_TOK / 128), 256, WGEMM_SMEM>>>(
            uh, wih, zx_p, M_TOK, D_IN_PROJ, D_MODEL);

    dt_kernel<<<(M_TOK * NHEADS) / 256, 256>>>(dt_bias);
    conv_silu_kernel<<<dim3(CONV_DIM / 128, M_TOK / 64), 256>>>(conv_w, conv_b);

    ssd1_tc<<<NBH * NCHUNK, 256>>>(A_log, Dv);
    ssd_phase2<<<NBH * 4, 256>>>();
    ssd3_tc<<<NBH * NCHUNK, 256>>>();

    gate_rms_kernel<<<M_TOK, 256>>>(norm_w, yh);

    // GEMM2: narrow tile (grid 8x64 = 512 CTAs at 2/SM, balanced waves)
    gemm_mma_kernel<float>
        <<<dim3(D_MODEL / 128, M_TOK / 128), 256, GEMM_SMEM>>>(
            yh, woh, out, M_TOK, D_MODEL, D_INNER);
}

// round 12
// speedup vs baseline: 1.2922x; 1.2922x over previous
#include <cuda_runtime.h>
#include <cuda_bf16.h>
#include <cuda_fp16.h>
#include <math.h>
#include <stdint.h>

#define D_MODEL   1024
#define D_STATE   64
#define D_CONV    4
#define D_INNER   2048
#define NHEADS    32
#define HEADDIM   64
#define CHUNK     64
#define CONV_DIM  2176
#define D_IN_PROJ 4256
#define B_SZ      2
#define T_LEN     4096
#define M_TOK     (B_SZ * T_LEN)   // 8192
#define NCHUNK    (T_LEN / CHUNK)  // 64
#define NBH       (B_SZ * NHEADS)  // 64

// ------------------------- scratch (device globals) -------------------------
__device__ __half g_zxbcdt[(size_t)M_TOK * D_IN_PROJ];
__device__ __half g_xbc[(size_t)M_TOK * CONV_DIM];
__device__ float  g_dt[(size_t)M_TOK * NHEADS];
__device__ __half g_y[(size_t)M_TOK * D_INNER];

__device__ __half g_uh[(size_t)M_TOK * D_MODEL];
__device__ __half g_wih[(size_t)D_IN_PROJ * D_MODEL];
__device__ __half g_yh[(size_t)M_TOK * D_INNER];
__device__ __half g_woh[(size_t)D_MODEL * D_INNER];

__device__ __half g_cs[(size_t)NBH * NCHUNK * 64 * 64];
__device__ __half g_ps[(size_t)NBH * NCHUNK * 64 * 64];
__device__ float  g_T[NBH * NCHUNK];
__device__ float  g_el[(size_t)NBH * NCHUNK * CHUNK];

// ------------------------- helpers ------------------------------------------
__device__ __forceinline__ uint32_t smem_u32(const void* p) {
    uint32_t a;
    asm("{ .reg .u64 t; cvta.to.shared.u64 t, %1; cvt.u32.u64 %0, t; }"
        : "=r"(a) : "l"(p));
    return a;
}
__device__ __forceinline__ void ldsm_x4(uint32_t& r0, uint32_t& r1,
                                        uint32_t& r2, uint32_t& r3,
                                        uint32_t addr) {
    asm volatile("ldmatrix.sync.aligned.m8n8.x4.shared.b16 {%0,%1,%2,%3}, [%4];"
                 : "=r"(r0), "=r"(r1), "=r"(r2), "=r"(r3) : "r"(addr));
}
__device__ __forceinline__ void ldsm_x4_t(uint32_t& r0, uint32_t& r1,
                                          uint32_t& r2, uint32_t& r3,
                                          uint32_t addr) {
    asm volatile("ldmatrix.sync.aligned.m8n8.x4.trans.shared.b16 {%0,%1,%2,%3}, [%4];"
                 : "=r"(r0), "=r"(r1), "=r"(r2), "=r"(r3) : "r"(addr));
}
__device__ __forceinline__ void mma_fp16(float* c, const uint32_t* a,
                                         uint32_t b0, uint32_t b1) {
    asm volatile(
        "mma.sync.aligned.m16n8k16.row.col.f32.f16.f16.f32 "
        "{%0,%1,%2,%3}, {%4,%5,%6,%7}, {%8,%9}, {%0,%1,%2,%3};"
        : "+f"(c[0]), "+f"(c[1]), "+f"(c[2]), "+f"(c[3])
        : "r"(a[0]), "r"(a[1]), "r"(a[2]), "r"(a[3]), "r"(b0), "r"(b1));
}
__device__ __forceinline__ void cp16(uint32_t dst, const void* src) {
    asm volatile("cp.async.cg.shared.global [%0], [%1], 16;"
                 :: "r"(dst), "l"(src));
}
__device__ __forceinline__ void cp16z(uint32_t dst, const void* src, int valid) {
    int sz = valid ? 16 : 0;
    asm volatile("cp.async.cg.shared.global [%0], [%1], 16, %2;"
                 :: "r"(dst), "l"(src), "r"(sz));
}
#define CP_COMMIT() asm volatile("cp.async.commit_group;" ::: "memory")
#define CP_WAIT(N)  asm volatile("cp.async.wait_group %0;" :: "n"(N) : "memory")

// 128B-row tile swizzle (rows of 64 halves)
__device__ __forceinline__ uint32_t swz128(int row, int cb) {
    return (uint32_t)(row * 128 + (cb ^ ((row & 7) << 4)));
}
__device__ __forceinline__ uint32_t packh2(float a, float b) {
    __half2 h = __floats2half2_rn(a, b);
    return *(uint32_t*)&h;
}
__device__ __forceinline__ float2 unpackh2(uint32_t w) {
    __half2 h = *(__half2*)&w;
    return make_float2(__half2float(h.x), __half2float(h.y));
}
__device__ __forceinline__ void store2(float* p, float a, float b) {
    *(float2*)p = make_float2(a, b);
}
__device__ __forceinline__ void store2(__half* p, float a, float b) {
    *(__half2*)p = __floats2half2_rn(a, b);
}

// ------------------------- fp32 -> fp16 convert -----------------------------
__global__ void cvt_kernel(const float* __restrict__ src,
                           __half* __restrict__ dst, int n) {
    int i = blockIdx.x * 256 + threadIdx.x;
    if (i * 2 < n) {
        float2 v = *(const float2*)(src + i * 2);
        *(__half2*)(dst + i * 2) = __floats2half2_rn(v.x, v.y);
    }
}

// ------------------------- HMMA GEMM: 128x128x64, 3 stages, 2 CTA/SM --------
// warp tile 64x32, fragment double-buffer across kk.
#define GTILE_B  16384                 // 128 x 64 halves
#define GSTAGE_B (2 * GTILE_B)         // 32 KB (A + B)
#define GNSTAGE  3
#define GEMM_SMEM (GNSTAGE * GSTAGE_B) // 96 KB
template <typename OT>
__global__ void __launch_bounds__(256, 2) gemm_mma_kernel(
    const __half* __restrict__ A, const __half* __restrict__ B,
    OT* __restrict__ C, int M, int N, int K) {
    extern __shared__ char smem[];
    const uint32_t sb = smem_u32(smem);

    const int tid  = threadIdx.x;
    const int wid  = tid >> 5;
    const int lane = tid & 31;
    const int m0 = blockIdx.y << 7;
    const int n0 = blockIdx.x << 7;
    const int wm0 = (wid >> 2) << 6;
    const int wn0 = (wid & 3) << 5;

    float acc[4][4][4];
#pragma unroll
    for (int f = 0; f < 4; f++)
#pragma unroll
        for (int g = 0; g < 4; g++)
#pragma unroll
            for (int e = 0; e < 4; e++) acc[f][g][e] = 0.f;

    const int nk = K >> 6;   // 64-wide K slabs

    auto load_stage = [&](int kc, int s) {
        const int k0 = kc << 6;
        const uint32_t st = sb + s * GSTAGE_B;
        // A: 128 rows x 128B = 1024 chunks
#pragma unroll
        for (int i = 0; i < 4; i++) {
            const int q = tid + (i << 8);
            const int r = q >> 3, j = q & 7;
            cp16(st + swz128(r, j * 16),
                 A + (size_t)(m0 + r) * K + k0 + j * 8);
        }
        // B: 1024 chunks, row-guarded
#pragma unroll
        for (int i = 0; i < 4; i++) {
            const int q = tid + (i << 8);
            const int r = q >> 3, j = q & 7;
            const int v = (n0 + r) < N;
            const size_t o = v ? (size_t)(n0 + r) * K + k0 + j * 8 : 0;
            cp16z(st + GTILE_B + swz128(r, j * 16), B + o, v);
        }
        CP_COMMIT();
    };

    load_stage(0, 0);
    if (nk > 1) load_stage(1, 1); else CP_COMMIT();

    const int a_row = lane & 15;
    const int a_kb  = (lane >> 4) << 4;
    const int b_row = (lane & 7) + ((lane >> 4) << 3);
    const int b_kb  = ((lane >> 3) & 1) << 4;

    uint32_t ah[2][4][4], bh[2][2][4];

    int s_cur = 0, s_n2 = 2;
    for (int kc = 0; kc < nk; kc++) {
        CP_WAIT(1);
        __syncthreads();
        if (kc + 2 < nk) load_stage(kc + 2, s_n2);
        else CP_COMMIT();

        const uint32_t st = sb + s_cur * GSTAGE_B;
        const uint32_t sA = st, sB = st + GTILE_B;

        // prime kk=0 fragments
        {
            const int kba = a_kb, kbb = b_kb;
#pragma unroll
            for (int f = 0; f < 4; f++)
                ldsm_x4(ah[0][f][0], ah[0][f][1], ah[0][f][2], ah[0][f][3],
                        sA + swz128(wm0 + f * 16 + a_row, kba));
#pragma unroll
            for (int g2 = 0; g2 < 2; g2++)
                ldsm_x4(bh[0][g2][0], bh[0][g2][1], bh[0][g2][2], bh[0][g2][3],
                        sB + swz128(wn0 + g2 * 16 + b_row, kbb));
        }
#pragma unroll
        for (int kk = 0; kk < 4; kk++) {
            const int cur = kk & 1, nxt = cur ^ 1;
            if (kk < 3) {
                const int kba = (kk + 1) * 32 + a_kb;
                const int kbb = (kk + 1) * 32 + b_kb;
#pragma unroll
                for (int f = 0; f < 4; f++)
                    ldsm_x4(ah[nxt][f][0], ah[nxt][f][1], ah[nxt][f][2],
                            ah[nxt][f][3],
                            sA + swz128(wm0 + f * 16 + a_row, kba));
#pragma unroll
                for (int g2 = 0; g2 < 2; g2++)
                    ldsm_x4(bh[nxt][g2][0], bh[nxt][g2][1], bh[nxt][g2][2],
                            bh[nxt][g2][3],
                            sB + swz128(wn0 + g2 * 16 + b_row, kbb));
            }
#pragma unroll
            for (int f = 0; f < 4; f++)
#pragma unroll
                for (int g = 0; g < 4; g++) {
                    const uint32_t* bf = &bh[cur][g >> 1][(g & 1) << 1];
                    mma_fp16(acc[f][g], ah[cur][f], bf[0], bf[1]);
                }
        }
        s_cur = (s_cur == 2) ? 0 : s_cur + 1;
        s_n2  = (s_n2  == 2) ? 0 : s_n2 + 1;
    }

    const int er = lane >> 2;
    const int ec = (lane & 3) << 1;
#pragma unroll
    for (int f = 0; f < 4; f++) {
        const int row = m0 + wm0 + f * 16 + er;
#pragma unroll
        for (int g = 0; g < 4; g++) {
            const int col = n0 + wn0 + g * 8 + ec;
            if (col < N) {
                store2(&C[(size_t)row * N + col], acc[f][g][0], acc[f][g][1]);
                store2(&C[(size_t)(row + 8) * N + col], acc[f][g][2],
                       acc[f][g][3]);
            }
        }
    }
}

// ------------------------- dt = softplus(raw + bias) ------------------------
__global__ void dt_kernel(const float* __restrict__ dt_bias) {
    const int idx = blockIdx.x * 256 + threadIdx.x;
    const int m = idx >> 5;
    const int h = idx & 31;
    float v = __half2float(
                  g_zxbcdt[(size_t)m * D_IN_PROJ + (D_INNER + CONV_DIM) + h]) +
              dt_bias[h];
    g_dt[idx] = (v > 20.f) ? v : log1pf(expf(v));
}

// ------------------------- tiled depthwise conv + SiLU (vectorized) ---------
__global__ void __launch_bounds__(256) conv_silu_kernel(
    const float* __restrict__ w, const float* __restrict__ bias) {
    __shared__ float sx[67][128];
    const int cb = blockIdx.x;
    const int tb = blockIdx.y;
    const int tid = threadIdx.x;
    const int m0 = tb * 64;
    const int zero_head = ((m0 & (T_LEN - 1)) == 0);

    for (int idx = tid; idx < 67 * 16; idx += 256) {
        const int r = idx >> 4, j = idx & 15;
        float4 z = make_float4(0.f, 0.f, 0.f, 0.f);
        uint4 raw = *(const uint4*)&z;
        if (r >= 3 || !zero_head)
            raw = *(const uint4*)&g_zxbcdt[(size_t)(m0 - 3 + r) * D_IN_PROJ +
                                           D_INNER + cb * 128 + j * 8];
        const uint32_t* hp = (const uint32_t*)&raw;
#pragma unroll
        for (int q = 0; q < 4; q++) {
            float2 v = unpackh2(hp[q]);
            sx[r][j * 8 + q * 2]     = v.x;
            sx[r][j * 8 + q * 2 + 1] = v.y;
        }
    }
    __syncthreads();

    const int ch = tid & 127;
    const int th = (tid >> 7) * 32;
    const int gc = cb * 128 + ch;
    const float w0 = w[gc * 4 + 0], w1 = w[gc * 4 + 1];
    const float w2 = w[gc * 4 + 2], w3 = w[gc * 4 + 3];
    const float bz = bias[gc];
#pragma unroll 8
    for (int i = 0; i < 32; i++) {
        const int t = th + i;
        float acc = bz + w0 * sx[t][ch] + w1 * sx[t + 1][ch] +
                    w2 * sx[t + 2][ch] + w3 * sx[t + 3][ch];
        g_xbc[(size_t)(m0 + t) * CONV_DIM + gc] =
            __float2half_rn(acc / (1.f + expf(-acc)));
    }
}

// ------------------------- SSD phase 1 (fp16 tensor cores) ------------------
#define OFF_X 0
#define OFF_B 8192
#define OFF_C 16384
#define OFF_M 24576
__global__ void __launch_bounds__(256) ssd1_tc(const float* __restrict__ A_log,
                                               const float* __restrict__ Dvec) {
    __shared__ __align__(16) char sm[32768];
    __shared__ float s_cum[64], s_dt[64], s_coef[64];
    const uint32_t sb = smem_u32(sm);

    const int blk = blockIdx.x;
    const int c   = blk & (NCHUNK - 1);
    const int bh  = blk >> 6;
    const int b = bh >> 5, h = bh & 31;
    const int tid = threadIdx.x, wid = tid >> 5, lane = tid & 31;
    const int r0 = (wid & 3) * 16, c0 = (wid >> 2) * 32;
    const int m0 = b * T_LEN + c * CHUNK;
    const float Ahc = -expf(A_log[h]);
    const float Dh  = Dvec[h];

#pragma unroll
    for (int i = 0; i < 6; i++) {
        int flat = tid + (i << 8);
        int t3 = flat >> 9;
        int wt = flat & 511;
        int l = wt >> 3, j = wt & 7;
        int off = (t3 == 0) ? h * HEADDIM : (t3 == 1) ? D_INNER
                                                      : D_INNER + D_STATE;
        cp16(sb + t3 * 8192 + swz128(l, j * 16),
             g_xbc + (size_t)(m0 + l) * CONV_DIM + off + j * 8);
    }
    CP_COMMIT();
    if (tid < 64) s_dt[tid] = g_dt[(size_t)(m0 + tid) * NHEADS + h];
    CP_WAIT(0);
    __syncthreads();
    if (wid == 0) {
        float v0 = Ahc * s_dt[lane * 2], v1 = Ahc * s_dt[lane * 2 + 1];
        float s = v0 + v1;
#pragma unroll
        for (int o = 1; o < 32; o <<= 1) {
            float t = __shfl_up_sync(0xFFFFFFFF, s, o);
            if (lane >= o) s += t;
        }
        float excl = s - (v0 + v1);
        s_cum[lane * 2] = excl + v0;
        s_cum[lane * 2 + 1] = excl + v0 + v1;
    }
    __syncthreads();
    if (tid < 64) {
        s_coef[tid] = s_dt[tid] * __expf(s_cum[63] - s_cum[tid]);
        g_el[(size_t)blk * 64 + tid] = __expf(s_cum[tid]);
    }
    if (tid == 0) g_T[blk] = __expf(s_cum[63]);
    __syncthreads();

    const int er = lane >> 2, ec = (lane & 3) << 1;

    // ---- step A: G = C @ B^T, mask/decay -> M (fp16) ----
    {
        float acc[4][4];
#pragma unroll
        for (int g = 0; g < 4; g++)
#pragma unroll
            for (int e = 0; e < 4; e++) acc[g][e] = 0.f;
#pragma unroll
        for (int k16 = 0; k16 < 4; k16++) {
            uint32_t ah[4];
            uint32_t aoff = swz128(r0 + (lane & 15),
                                   k16 * 32 + ((lane >> 4) << 4));
            ldsm_x4(ah[0], ah[1], ah[2], ah[3], sb + OFF_C + aoff);
            uint32_t bhf[2][4];
#pragma unroll
            for (int g2 = 0; g2 < 2; g2++) {
                uint32_t boff =
                    swz128(c0 + g2 * 16 + (lane & 7) + ((lane >> 4) << 3),
                           k16 * 32 + (((lane >> 3) & 1) << 4));
                ldsm_x4(bhf[g2][0], bhf[g2][1], bhf[g2][2], bhf[g2][3],
                        sb + OFF_B + boff);
            }
#pragma unroll
            for (int g = 0; g < 4; g++) {
                const uint32_t* bf = &bhf[g >> 1][(g & 1) << 1];
                mma_fp16(acc[g], ah, bf[0], bf[1]);
            }
        }
#pragma unroll
        for (int g = 0; g < 4; g++) {
            int s0 = c0 + g * 8 + ec;
            float cs0 = s_cum[s0], cs1 = s_cum[s0 + 1];
            float d0 = s_dt[s0], d1 = s_dt[s0 + 1];
#pragma unroll
            for (int hf = 0; hf < 2; hf++) {
                int l = r0 + er + hf * 8;
                float cl = s_cum[l];
                float v0 = (s0     <= l) ? acc[g][hf * 2 + 0] * __expf(cl - cs0) * d0 : 0.f;
                float v1 = (s0 + 1 <= l) ? acc[g][hf * 2 + 1] * __expf(cl - cs1) * d1 : 0.f;
                *(uint32_t*)(sm + OFF_M + swz128(l, s0 * 2)) = packh2(v0, v1);
            }
        }
    }
    __syncthreads();

    // ---- CX = coef(l) * x (overwrites C tile) ----
#pragma unroll
    for (int i = 0; i < 8; i++) {
        int flat = tid + (i << 8);
        int l = flat >> 5, q2 = flat & 31;
        uint32_t so = swz128(l, q2 * 4);
        float2 v = unpackh2(*(uint32_t*)(sm + OFF_X + so));
        float cf = s_coef[l];
        *(uint32_t*)(sm + OFF_C + so) = packh2(v.x * cf, v.y * cf);
    }

    // ---- step B: Y = M @ x (+ D skip) -> fp16 g_y ----
    {
        float acc[4][4];
#pragma unroll
        for (int g = 0; g < 4; g++)
#pragma unroll
            for (int e = 0; e < 4; e++) acc[g][e] = 0.f;
#pragma unroll
        for (int k16 = 0; k16 < 4; k16++) {
            uint32_t ah[4];
            uint32_t aoff = swz128(r0 + (lane & 15),
                                   k16 * 32 + ((lane >> 4) << 4));
            ldsm_x4(ah[0], ah[1], ah[2], ah[3], sb + OFF_M + aoff);
            uint32_t bhf[2][4];
#pragma unroll
            for (int g2 = 0; g2 < 2; g2++) {
                uint32_t boff =
                    swz128(k16 * 16 + ((lane >> 3) & 1) * 8 + (lane & 7),
                           (c0 + g2 * 16) * 2 + (((lane >> 4) & 1) << 4));
                ldsm_x4_t(bhf[g2][0], bhf[g2][1], bhf[g2][2], bhf[g2][3],
                          sb + OFF_X + boff);
            }
#pragma unroll
            for (int g = 0; g < 4; g++) {
                const uint32_t* bf = &bhf[g >> 1][(g & 1) << 1];
                mma_fp16(acc[g], ah, bf[0], bf[1]);
            }
        }
#pragma unroll
        for (int g = 0; g < 4; g++) {
            int p0 = c0 + g * 8 + ec;
#pragma unroll
            for (int hf = 0; hf < 2; hf++) {
                int l = r0 + er + hf * 8;
                float2 xv = unpackh2(*(uint32_t*)(sm + OFF_X + swz128(l, p0 * 2)));
                *(uint32_t*)&g_y[(size_t)(m0 + l) * D_INNER + h * HEADDIM + p0] =
                    packh2(acc[g][hf * 2 + 0] + Dh * xv.x,
                           acc[g][hf * 2 + 1] + Dh * xv.y);
            }
        }
    }
    __syncthreads();

    // ---- step C: S(p,n) = CX^T @ B -> fp16 g_cs ----
    {
        float acc[4][4];
#pragma unroll
        for (int g = 0; g < 4; g++)
#pragma unroll
            for (int e = 0; e < 4; e++) acc[g][e] = 0.f;
#pragma unroll
        for (int k16 = 0; k16 < 4; k16++) {
            uint32_t ah[4];
            uint32_t aoff =
                swz128(k16 * 16 + ((lane >> 4) & 1) * 8 + (lane & 7),
                       r0 * 2 + (((lane >> 3) & 1) << 4));
            ldsm_x4_t(ah[0], ah[1], ah[2], ah[3], sb + OFF_C + aoff);
            uint32_t bhf[2][4];
#pragma unroll
            for (int g2 = 0; g2 < 2; g2++) {
                uint32_t boff =
                    swz128(k16 * 16 + ((lane >> 3) & 1) * 8 + (lane & 7),
                           (c0 + g2 * 16) * 2 + (((lane >> 4) & 1) << 4));
                ldsm_x4_t(bhf[g2][0], bhf[g2][1], bhf[g2][2], bhf[g2][3],
                          sb + OFF_B + boff);
            }
#pragma unroll
            for (int g = 0; g < 4; g++) {
                const uint32_t* bf = &bhf[g >> 1][(g & 1) << 1];
                mma_fp16(acc[g], ah, bf[0], bf[1]);
            }
        }
        const size_t sbase = (size_t)blk * 4096;
#pragma unroll
        for (int g = 0; g < 4; g++) {
            int n0 = c0 + g * 8 + ec;
#pragma unroll
            for (int hf = 0; hf < 2; hf++) {
                int p = r0 + er + hf * 8;
                *(uint32_t*)&g_cs[sbase + p * 64 + n0] =
                    packh2(acc[g][hf * 2 + 0], acc[g][hf * 2 + 1]);
            }
        }
    }
}

// ------------------------- SSD phase 2: scan (4x par, prefetched, uint2) ----
__global__ void __launch_bounds__(256) ssd_phase2() {
    __shared__ float sT[NCHUNK];
    const int slice = blockIdx.x & 3;
    const int bh    = blockIdx.x >> 2;
    const int tid   = threadIdx.x;
    if (tid < NCHUNK) sT[tid] = g_T[bh * NCHUNK + tid];
    __syncthreads();

    const int off = slice * 1024 + tid * 4;
    const size_t b0 = (size_t)bh * NCHUNK * 4096 + off;
    float s0 = 0.f, s1 = 0.f, s2 = 0.f, s3 = 0.f;
    uint2 nxt = *(const uint2*)&g_cs[b0];
#pragma unroll 4
    for (int c = 0; c < NCHUNK; c++) {
        const size_t base = b0 + (size_t)c * 4096;
        uint2 st;
        st.x = packh2(s0, s1);
        st.y = packh2(s2, s3);
        *(uint2*)&g_ps[base] = st;
        const uint2 cur = nxt;
        if (c + 1 < NCHUNK) nxt = *(const uint2*)&g_cs[base + 4096];
        const float T = sT[c];
        float2 v0 = unpackh2(cur.x);
        float2 v1 = unpackh2(cur.y);
        s0 = s0 * T + v0.x;
        s1 = s1 * T + v0.y;
        s2 = s2 * T + v1.x;
        s3 = s3 * T + v1.y;
    }
}

// ------------------------- SSD phase 3 (fp16 tensor cores) ------------------
__global__ void __launch_bounds__(256) ssd3_tc() {
    __shared__ __align__(16) char t_C[8192];
    __shared__ __align__(16) char t_S[8192];
    __shared__ float s_el[64];
    const uint32_t aC = smem_u32(t_C), aS = smem_u32(t_S);

    const int blk = blockIdx.x;
    const int c   = blk & (NCHUNK - 1);
    const int bh  = blk >> 6;
    const int b = bh >> 5, h = bh & 31;
    const int tid = threadIdx.x, wid = tid >> 5, lane = tid & 31;
    const int r0 = (wid & 3) * 16, c0 = (wid >> 2) * 32;
    const int m0 = b * T_LEN + c * CHUNK;

#pragma unroll
    for (int i = 0; i < 2; i++) {
        int flat = tid + (i << 8);
        int l = flat >> 3, j = flat & 7;
        cp16(aC + swz128(l, j * 16),
             g_xbc + (size_t)(m0 + l) * CONV_DIM + D_INNER + D_STATE + j * 8);
        cp16(aS + swz128(l, j * 16),
             g_ps + (size_t)blk * 4096 + l * 64 + j * 8);
    }
    CP_COMMIT();
    if (tid < 64) s_el[tid] = g_el[(size_t)blk * 64 + tid];
    CP_WAIT(0);
    __syncthreads();

    float acc[4][4];
#pragma unroll
    for (int g = 0; g < 4; g++)
#pragma unroll
        for (int e = 0; e < 4; e++) acc[g][e] = 0.f;
#pragma unroll
    for (int k16 = 0; k16 < 4; k16++) {
        uint32_t ah[4];
        uint32_t aoff = swz128(r0 + (lane & 15), k16 * 32 + ((lane >> 4) << 4));
        ldsm_x4(ah[0], ah[1], ah[2], ah[3], aC + aoff);
        uint32_t bhf[2][4];
#pragma unroll
        for (int g2 = 0; g2 < 2; g2++) {
            uint32_t boff =
                swz128(c0 + g2 * 16 + (lane & 7) + ((lane >> 4) << 3),
                       k16 * 32 + (((lane >> 3) & 1) << 4));
            ldsm_x4(bhf[g2][0], bhf[g2][1], bhf[g2][2], bhf[g2][3], aS + boff);
        }
#pragma unroll
        for (int g = 0; g < 4; g++) {
            const uint32_t* bf = &bhf[g >> 1][(g & 1) << 1];
            mma_fp16(acc[g], ah, bf[0], bf[1]);
        }
    }
    const int er = lane >> 2, ec = (lane & 3) << 1;
#pragma unroll
    for (int g = 0; g < 4; g++) {
        int p0 = c0 + g * 8 + ec;
#pragma unroll
        for (int hf = 0; hf < 2; hf++) {
            int l = r0 + er + hf * 8;
            float el = s_el[l];
            uint32_t* yp =
                (uint32_t*)&g_y[(size_t)(m0 + l) * D_INNER + h * HEADDIM + p0];
            float2 cur = unpackh2(*yp);
            *yp = packh2(cur.x + el * acc[g][hf * 2 + 0],
                         cur.y + el * acc[g][hf * 2 + 1]);
        }
    }
}

// ------------------------- gate + RMSNorm -> fp16 (vectorized) --------------
__global__ void gate_rms_kernel(const float* __restrict__ norm_w,
                                __half* __restrict__ yh) {
    const int m = blockIdx.x;
    const int tid = threadIdx.x;
    const size_t ybase = (size_t)m * D_INNER;
    const size_t zbase = (size_t)m * D_IN_PROJ;
    const int i0 = tid * 8;

    uint4 yraw = *(const uint4*)&g_y[ybase + i0];
    uint4 zraw = *(const uint4*)&g_zxbcdt[zbase + i0];
    float vals[8];
    float ssum = 0.f;
    const uint32_t* yw = (const uint32_t*)&yraw;
    const uint32_t* zw = (const uint32_t*)&zraw;
#pragma unroll
    for (int q = 0; q < 4; q++) {
        float2 yv = unpackh2(yw[q]);
        float2 zv = unpackh2(zw[q]);
        float g0 = yv.x * zv.x / (1.f + expf(-zv.x));
        float g1 = yv.y * zv.y / (1.f + expf(-zv.y));
        vals[q * 2] = g0;
        vals[q * 2 + 1] = g1;
        ssum += g0 * g0 + g1 * g1;
    }
    __shared__ float red[256];
    red[tid] = ssum;
    __syncthreads();
    for (int s = 128; s > 0; s >>= 1) {
        if (tid < s) red[tid] += red[tid + s];
        __syncthreads();
    }
    const float scale = rsqrtf(red[0] / (float)D_INNER + 1e-5f);

    float4 w0 = *(const float4*)&norm_w[i0];
    float4 w1 = *(const float4*)&norm_w[i0 + 4];
    uint4 outw;
    uint32_t* ow = (uint32_t*)&outw;
    ow[0] = packh2(vals[0] * scale * w0.x, vals[1] * scale * w0.y);
    ow[1] = packh2(vals[2] * scale * w0.z, vals[3] * scale * w0.w);
    ow[2] = packh2(vals[4] * scale * w1.x, vals[5] * scale * w1.y);
    ow[3] = packh2(vals[6] * scale * w1.z, vals[7] * scale * w1.w);
    *(uint4*)&yh[ybase + i0] = outw;
}

// ---------------------------------------------------------------------------
extern "C" void kernel_launch(void* const* d_in, const int* in_sizes, int n_in,
                              void* d_out, int out_size) {
    const float* u       = (const float*)d_in[0];
    const float* W_in    = (const float*)d_in[1];
    const float* conv_w  = (const float*)d_in[2];
    const float* conv_b  = (const float*)d_in[3];
    const float* dt_bias = (const float*)d_in[4];
    const float* A_log   = (const float*)d_in[5];
    const float* Dv      = (const float*)d_in[6];
    const float* norm_w  = (const float*)d_in[7];
    const float* W_out   = (const float*)d_in[8];
    float* out = (float*)d_out;

    __half *zx_p, *uh, *wih, *yh, *woh;
    cudaGetSymbolAddress((void**)&zx_p, g_zxbcdt);
    cudaGetSymbolAddress((void**)&uh, g_uh);
    cudaGetSymbolAddress((void**)&wih, g_wih);
    cudaGetSymbolAddress((void**)&yh, g_yh);
    cudaGetSymbolAddress((void**)&woh, g_woh);

    cudaFuncSetAttribute(gemm_mma_kernel<__half>,
                         cudaFuncAttributeMaxDynamicSharedMemorySize, GEMM_SMEM);
    cudaFuncSetAttribute(gemm_mma_kernel<float>,
                         cudaFuncAttributeMaxDynamicSharedMemorySize, GEMM_SMEM);

    {
        int n = M_TOK * D_MODEL;
        cvt_kernel<<<(n / 2 + 255) / 256, 256>>>(u, uh, n);
        n = D_IN_PROJ * D_MODEL;
        cvt_kernel<<<(n / 2 + 255) / 256, 256>>>(W_in, wih, n);
        n = D_MODEL * D_INNER;
        cvt_kernel<<<(n / 2 + 255) / 256, 256>>>(W_out, woh, n);
    }

    gemm_mma_kernel<__half>
        <<<dim3((D_IN_PROJ + 127) / 128, M_TOK / 128), 256, GEMM_SMEM>>>(
            uh, wih, zx_p, M_TOK, D_IN_PROJ, D_MODEL);

    dt_kernel<<<(M_TOK * NHEADS) / 256, 256>>>(dt_bias);
    conv_silu_kernel<<<dim3(CONV_DIM / 128, M_TOK / 64), 256>>>(conv_w, conv_b);

    ssd1_tc<<<NBH * NCHUNK, 256>>>(A_log, Dv);
    ssd_phase2<<<NBH * 4, 256>>>();
    ssd3_tc<<<NBH * NCHUNK, 256>>>();

    gate_rms_kernel<<<M_TOK, 256>>>(norm_w, yh);

    gemm_mma_kernel<float>
        <<<dim3(D_MODEL / 128, M_TOK / 128), 256, GEMM_SMEM>>>(
            yh, woh, out, M_TOK, D_MODEL, D_INNER);
}

// round 13
// speedup vs baseline: 1.3228x; 1.0237x over previous
#include <cuda_runtime.h>
#include <cuda_bf16.h>
#include <cuda_fp16.h>
#include <math.h>
#include <stdint.h>

#define D_MODEL   1024
#define D_STATE   64
#define D_CONV    4
#define D_INNER   2048
#define NHEADS    32
#define HEADDIM   64
#define CHUNK     64
#define CONV_DIM  2176
#define D_IN_PROJ 4256
#define B_SZ      2
#define T_LEN     4096
#define M_TOK     (B_SZ * T_LEN)   // 8192
#define NCHUNK    (T_LEN / CHUNK)  // 64
#define NBH       (B_SZ * NHEADS)  // 64

// ------------------------- scratch (device globals) -------------------------
__device__ __half g_zxbcdt[(size_t)M_TOK * D_IN_PROJ];
__device__ __half g_xbc[(size_t)M_TOK * CONV_DIM];
__device__ float  g_dt[(size_t)M_TOK * NHEADS];
__device__ __half g_y[(size_t)M_TOK * D_INNER];

__device__ __half g_uh[(size_t)M_TOK * D_MODEL];
__device__ __half g_wih[(size_t)D_IN_PROJ * D_MODEL];
__device__ __half g_yh[(size_t)M_TOK * D_INNER];
__device__ __half g_woh[(size_t)D_MODEL * D_INNER];

__device__ __half g_cs[(size_t)NBH * NCHUNK * 64 * 64];
__device__ __half g_ps[(size_t)NBH * NCHUNK * 64 * 64];
__device__ float  g_T[NBH * NCHUNK];
__device__ float  g_el[(size_t)NBH * NCHUNK * CHUNK];

// ------------------------- helpers ------------------------------------------
__device__ __forceinline__ uint32_t smem_u32(const void* p) {
    uint32_t a;
    asm("{ .reg .u64 t; cvta.to.shared.u64 t, %1; cvt.u32.u64 %0, t; }"
        : "=r"(a) : "l"(p));
    return a;
}
__device__ __forceinline__ void ldsm_x4(uint32_t& r0, uint32_t& r1,
                                        uint32_t& r2, uint32_t& r3,
                                        uint32_t addr) {
    asm volatile("ldmatrix.sync.aligned.m8n8.x4.shared.b16 {%0,%1,%2,%3}, [%4];"
                 : "=r"(r0), "=r"(r1), "=r"(r2), "=r"(r3) : "r"(addr));
}
__device__ __forceinline__ void ldsm_x4_t(uint32_t& r0, uint32_t& r1,
                                          uint32_t& r2, uint32_t& r3,
                                          uint32_t addr) {
    asm volatile("ldmatrix.sync.aligned.m8n8.x4.trans.shared.b16 {%0,%1,%2,%3}, [%4];"
                 : "=r"(r0), "=r"(r1), "=r"(r2), "=r"(r3) : "r"(addr));
}
__device__ __forceinline__ void mma_fp16(float* c, const uint32_t* a,
                                         uint32_t b0, uint32_t b1) {
    asm volatile(
        "mma.sync.aligned.m16n8k16.row.col.f32.f16.f16.f32 "
        "{%0,%1,%2,%3}, {%4,%5,%6,%7}, {%8,%9}, {%0,%1,%2,%3};"
        : "+f"(c[0]), "+f"(c[1]), "+f"(c[2]), "+f"(c[3])
        : "r"(a[0]), "r"(a[1]), "r"(a[2]), "r"(a[3]), "r"(b0), "r"(b1));
}
__device__ __forceinline__ void cp16(uint32_t dst, const void* src) {
    asm volatile("cp.async.cg.shared.global [%0], [%1], 16;"
                 :: "r"(dst), "l"(src));
}
__device__ __forceinline__ void cp16z(uint32_t dst, const void* src, int valid) {
    int sz = valid ? 16 : 0;
    asm volatile("cp.async.cg.shared.global [%0], [%1], 16, %2;"
                 :: "r"(dst), "l"(src), "r"(sz));
}
#define CP_COMMIT() asm volatile("cp.async.commit_group;" ::: "memory")
#define CP_WAIT(N)  asm volatile("cp.async.wait_group %0;" :: "n"(N) : "memory")

// 128B-row tile swizzle (rows of 64 halves)
__device__ __forceinline__ uint32_t swz128(int row, int cb) {
    return (uint32_t)(row * 128 + (cb ^ ((row & 7) << 4)));
}
__device__ __forceinline__ uint32_t packh2(float a, float b) {
    __half2 h = __floats2half2_rn(a, b);
    return *(uint32_t*)&h;
}
__device__ __forceinline__ float2 unpackh2(uint32_t w) {
    __half2 h = *(__half2*)&w;
    return make_float2(__half2float(h.x), __half2float(h.y));
}
__device__ __forceinline__ void store2(float* p, float a, float b) {
    *(float2*)p = make_float2(a, b);
}
__device__ __forceinline__ void store2(__half* p, float a, float b) {
    *(__half2*)p = __floats2half2_rn(a, b);
}

// ------------------------- fp32 -> fp16 convert -----------------------------
__global__ void cvt_kernel(const float* __restrict__ src,
                           __half* __restrict__ dst, int n) {
    int i = blockIdx.x * 256 + threadIdx.x;
    if (i * 2 < n) {
        float2 v = *(const float2*)(src + i * 2);
        *(__half2*)(dst + i * 2) = __floats2half2_rn(v.x, v.y);
    }
}

// ------------------------- HMMA GEMM: 128x128x64, 4 warps, 2 CTA/SM ---------
// warp tile 64x64 (2x2 warp grid), fragment double-buffer, 3-stage cp.async.
// 8 ldsm_x4 per 32 mma per kk -> 128 B/mma -> smem crossbar no longer binds.
#define GTILE_B  16384                 // 128 x 64 halves
#define GSTAGE_B (2 * GTILE_B)         // 32 KB (A + B)
#define GNSTAGE  3
#define GEMM_SMEM (GNSTAGE * GSTAGE_B) // 96 KB
template <typename OT>
__global__ void __launch_bounds__(128, 2) gemm_mma_kernel(
    const __half* __restrict__ A, const __half* __restrict__ B,
    OT* __restrict__ C, int M, int N, int K) {
    extern __shared__ char smem[];
    const uint32_t sb = smem_u32(smem);

    const int tid  = threadIdx.x;
    const int wid  = tid >> 5;
    const int lane = tid & 31;
    const int m0 = blockIdx.y << 7;
    const int n0 = blockIdx.x << 7;
    const int wm0 = (wid >> 1) << 6;    // 0 or 64
    const int wn0 = (wid & 1) << 6;     // 0 or 64

    float acc[4][8][4];
#pragma unroll
    for (int f = 0; f < 4; f++)
#pragma unroll
        for (int g = 0; g < 8; g++)
#pragma unroll
            for (int e = 0; e < 4; e++) acc[f][g][e] = 0.f;

    const int nk = K >> 6;   // 64-wide K slabs

    auto load_stage = [&](int kc, int s) {
        const int k0 = kc << 6;
        const uint32_t st = sb + s * GSTAGE_B;
        // A: 1024 chunks of 16B, 128 threads -> 8 per thread
#pragma unroll
        for (int i = 0; i < 8; i++) {
            const int q = tid + (i << 7);
            const int r = q >> 3, j = q & 7;
            cp16(st + swz128(r, j * 16),
                 A + (size_t)(m0 + r) * K + k0 + j * 8);
        }
        // B: 1024 chunks, row-guarded
#pragma unroll
        for (int i = 0; i < 8; i++) {
            const int q = tid + (i << 7);
            const int r = q >> 3, j = q & 7;
            const int v = (n0 + r) < N;
            const size_t o = v ? (size_t)(n0 + r) * K + k0 + j * 8 : 0;
            cp16z(st + GTILE_B + swz128(r, j * 16), B + o, v);
        }
        CP_COMMIT();
    };

    load_stage(0, 0);
    if (nk > 1) load_stage(1, 1); else CP_COMMIT();

    const int a_row = lane & 15;
    const int a_kb  = (lane >> 4) << 4;
    const int b_row = (lane & 7) + ((lane >> 4) << 3);
    const int b_kb  = ((lane >> 3) & 1) << 4;

    uint32_t ah[2][4][4], bh[2][4][4];

    int s_cur = 0, s_n2 = 2;
    for (int kc = 0; kc < nk; kc++) {
        CP_WAIT(1);
        __syncthreads();
        if (kc + 2 < nk) load_stage(kc + 2, s_n2);
        else CP_COMMIT();

        const uint32_t st = sb + s_cur * GSTAGE_B;
        const uint32_t sA = st, sB = st + GTILE_B;

        // prime kk=0 fragments
        {
#pragma unroll
            for (int f = 0; f < 4; f++)
                ldsm_x4(ah[0][f][0], ah[0][f][1], ah[0][f][2], ah[0][f][3],
                        sA + swz128(wm0 + f * 16 + a_row, a_kb));
#pragma unroll
            for (int g2 = 0; g2 < 4; g2++)
                ldsm_x4(bh[0][g2][0], bh[0][g2][1], bh[0][g2][2], bh[0][g2][3],
                        sB + swz128(wn0 + g2 * 16 + b_row, b_kb));
        }
#pragma unroll
        for (int kk = 0; kk < 4; kk++) {
            const int cur = kk & 1, nxt = cur ^ 1;
            if (kk < 3) {
                const int kba = (kk + 1) * 32 + a_kb;
                const int kbb = (kk + 1) * 32 + b_kb;
#pragma unroll
                for (int f = 0; f < 4; f++)
                    ldsm_x4(ah[nxt][f][0], ah[nxt][f][1], ah[nxt][f][2],
                            ah[nxt][f][3],
                            sA + swz128(wm0 + f * 16 + a_row, kba));
#pragma unroll
                for (int g2 = 0; g2 < 4; g2++)
                    ldsm_x4(bh[nxt][g2][0], bh[nxt][g2][1], bh[nxt][g2][2],
                            bh[nxt][g2][3],
                            sB + swz128(wn0 + g2 * 16 + b_row, kbb));
            }
#pragma unroll
            for (int f = 0; f < 4; f++)
#pragma unroll
                for (int g = 0; g < 8; g++) {
                    const uint32_t* bf = &bh[cur][g >> 1][(g & 1) << 1];
                    mma_fp16(acc[f][g], ah[cur][f], bf[0], bf[1]);
                }
        }
        s_cur = (s_cur == 2) ? 0 : s_cur + 1;
        s_n2  = (s_n2  == 2) ? 0 : s_n2 + 1;
    }

    const int er = lane >> 2;
    const int ec = (lane & 3) << 1;
#pragma unroll
    for (int f = 0; f < 4; f++) {
        const int row = m0 + wm0 + f * 16 + er;
#pragma unroll
        for (int g = 0; g < 8; g++) {
            const int col = n0 + wn0 + g * 8 + ec;
            if (col < N) {
                store2(&C[(size_t)row * N + col], acc[f][g][0], acc[f][g][1]);
                store2(&C[(size_t)(row + 8) * N + col], acc[f][g][2],
                       acc[f][g][3]);
            }
        }
    }
}

// ------------------------- dt = softplus(raw + bias) ------------------------
__global__ void dt_kernel(const float* __restrict__ dt_bias) {
    const int idx = blockIdx.x * 256 + threadIdx.x;
    const int m = idx >> 5;
    const int h = idx & 31;
    float v = __half2float(
                  g_zxbcdt[(size_t)m * D_IN_PROJ + (D_INNER + CONV_DIM) + h]) +
              dt_bias[h];
    g_dt[idx] = (v > 20.f) ? v : log1pf(expf(v));
}

// ------------------------- tiled depthwise conv + SiLU (vectorized) ---------
__global__ void __launch_bounds__(256) conv_silu_kernel(
    const float* __restrict__ w, const float* __restrict__ bias) {
    __shared__ float sx[67][128];
    const int cb = blockIdx.x;
    const int tb = blockIdx.y;
    const int tid = threadIdx.x;
    const int m0 = tb * 64;
    const int zero_head = ((m0 & (T_LEN - 1)) == 0);

    for (int idx = tid; idx < 67 * 16; idx += 256) {
        const int r = idx >> 4, j = idx & 15;
        float4 z = make_float4(0.f, 0.f, 0.f, 0.f);
        uint4 raw = *(const uint4*)&z;
        if (r >= 3 || !zero_head)
            raw = *(const uint4*)&g_zxbcdt[(size_t)(m0 - 3 + r) * D_IN_PROJ +
                                           D_INNER + cb * 128 + j * 8];
        const uint32_t* hp = (const uint32_t*)&raw;
#pragma unroll
        for (int q = 0; q < 4; q++) {
            float2 v = unpackh2(hp[q]);
            sx[r][j * 8 + q * 2]     = v.x;
            sx[r][j * 8 + q * 2 + 1] = v.y;
        }
    }
    __syncthreads();

    const int ch = tid & 127;
    const int th = (tid >> 7) * 32;
    const int gc = cb * 128 + ch;
    const float w0 = w[gc * 4 + 0], w1 = w[gc * 4 + 1];
    const float w2 = w[gc * 4 + 2], w3 = w[gc * 4 + 3];
    const float bz = bias[gc];
#pragma unroll 8
    for (int i = 0; i < 32; i++) {
        const int t = th + i;
        float acc = bz + w0 * sx[t][ch] + w1 * sx[t + 1][ch] +
                    w2 * sx[t + 2][ch] + w3 * sx[t + 3][ch];
        g_xbc[(size_t)(m0 + t) * CONV_DIM + gc] =
            __float2half_rn(acc / (1.f + expf(-acc)));
    }
}

// ------------------------- SSD phase 1 (fp16 tensor cores) ------------------
#define OFF_X 0
#define OFF_B 8192
#define OFF_C 16384
#define OFF_M 24576
__global__ void __launch_bounds__(256) ssd1_tc(const float* __restrict__ A_log,
                                               const float* __restrict__ Dvec) {
    __shared__ __align__(16) char sm[32768];
    __shared__ float s_cum[64], s_dt[64], s_coef[64];
    const uint32_t sb = smem_u32(sm);

    const int blk = blockIdx.x;
    const int c   = blk & (NCHUNK - 1);
    const int bh  = blk >> 6;
    const int b = bh >> 5, h = bh & 31;
    const int tid = threadIdx.x, wid = tid >> 5, lane = tid & 31;
    const int r0 = (wid & 3) * 16, c0 = (wid >> 2) * 32;
    const int m0 = b * T_LEN + c * CHUNK;
    const float Ahc = -expf(A_log[h]);
    const float Dh  = Dvec[h];

#pragma unroll
    for (int i = 0; i < 6; i++) {
        int flat = tid + (i << 8);
        int t3 = flat >> 9;
        int wt = flat & 511;
        int l = wt >> 3, j = wt & 7;
        int off = (t3 == 0) ? h * HEADDIM : (t3 == 1) ? D_INNER
                                                      : D_INNER + D_STATE;
        cp16(sb + t3 * 8192 + swz128(l, j * 16),
             g_xbc + (size_t)(m0 + l) * CONV_DIM + off + j * 8);
    }
    CP_COMMIT();
    if (tid < 64) s_dt[tid] = g_dt[(size_t)(m0 + tid) * NHEADS + h];
    CP_WAIT(0);
    __syncthreads();
    if (wid == 0) {
        float v0 = Ahc * s_dt[lane * 2], v1 = Ahc * s_dt[lane * 2 + 1];
        float s = v0 + v1;
#pragma unroll
        for (int o = 1; o < 32; o <<= 1) {
            float t = __shfl_up_sync(0xFFFFFFFF, s, o);
            if (lane >= o) s += t;
        }
        float excl = s - (v0 + v1);
        s_cum[lane * 2] = excl + v0;
        s_cum[lane * 2 + 1] = excl + v0 + v1;
    }
    __syncthreads();
    if (tid < 64) {
        s_coef[tid] = s_dt[tid] * __expf(s_cum[63] - s_cum[tid]);
        g_el[(size_t)blk * 64 + tid] = __expf(s_cum[tid]);
    }
    if (tid == 0) g_T[blk] = __expf(s_cum[63]);
    __syncthreads();

    const int er = lane >> 2, ec = (lane & 3) << 1;

    // ---- step A: G = C @ B^T, mask/decay -> M (fp16) ----
    {
        float acc[4][4];
#pragma unroll
        for (int g = 0; g < 4; g++)
#pragma unroll
            for (int e = 0; e < 4; e++) acc[g][e] = 0.f;
#pragma unroll
        for (int k16 = 0; k16 < 4; k16++) {
            uint32_t ah[4];
            uint32_t aoff = swz128(r0 + (lane & 15),
                                   k16 * 32 + ((lane >> 4) << 4));
            ldsm_x4(ah[0], ah[1], ah[2], ah[3], sb + OFF_C + aoff);
            uint32_t bhf[2][4];
#pragma unroll
            for (int g2 = 0; g2 < 2; g2++) {
                uint32_t boff =
                    swz128(c0 + g2 * 16 + (lane & 7) + ((lane >> 4) << 3),
                           k16 * 32 + (((lane >> 3) & 1) << 4));
                ldsm_x4(bhf[g2][0], bhf[g2][1], bhf[g2][2], bhf[g2][3],
                        sb + OFF_B + boff);
            }
#pragma unroll
            for (int g = 0; g < 4; g++) {
                const uint32_t* bf = &bhf[g >> 1][(g & 1) << 1];
                mma_fp16(acc[g], ah, bf[0], bf[1]);
            }
        }
#pragma unroll
        for (int g = 0; g < 4; g++) {
            int s0 = c0 + g * 8 + ec;
            float cs0 = s_cum[s0], cs1 = s_cum[s0 + 1];
            float d0 = s_dt[s0], d1 = s_dt[s0 + 1];
#pragma unroll
            for (int hf = 0; hf < 2; hf++) {
                int l = r0 + er + hf * 8;
                float cl = s_cum[l];
                float v0 = (s0     <= l) ? acc[g][hf * 2 + 0] * __expf(cl - cs0) * d0 : 0.f;
                float v1 = (s0 + 1 <= l) ? acc[g][hf * 2 + 1] * __expf(cl - cs1) * d1 : 0.f;
                *(uint32_t*)(sm + OFF_M + swz128(l, s0 * 2)) = packh2(v0, v1);
            }
        }
    }
    __syncthreads();

    // ---- CX = coef(l) * x (overwrites C tile) ----
#pragma unroll
    for (int i = 0; i < 8; i++) {
        int flat = tid + (i << 8);
        int l = flat >> 5, q2 = flat & 31;
        uint32_t so = swz128(l, q2 * 4);
        float2 v = unpackh2(*(uint32_t*)(sm + OFF_X + so));
        float cf = s_coef[l];
        *(uint32_t*)(sm + OFF_C + so) = packh2(v.x * cf, v.y * cf);
    }

    // ---- step B: Y = M @ x (+ D skip) -> fp16 g_y ----
    {
        float acc[4][4];
#pragma unroll
        for (int g = 0; g < 4; g++)
#pragma unroll
            for (int e = 0; e < 4; e++) acc[g][e] = 0.f;
#pragma unroll
        for (int k16 = 0; k16 < 4; k16++) {
            uint32_t ah[4];
            uint32_t aoff = swz128(r0 + (lane & 15),
                                   k16 * 32 + ((lane >> 4) << 4));
            ldsm_x4(ah[0], ah[1], ah[2], ah[3], sb + OFF_M + aoff);
            uint32_t bhf[2][4];
#pragma unroll
            for (int g2 = 0; g2 < 2; g2++) {
                uint32_t boff =
                    swz128(k16 * 16 + ((lane >> 3) & 1) * 8 + (lane & 7),
                           (c0 + g2 * 16) * 2 + (((lane >> 4) & 1) << 4));
                ldsm_x4_t(bhf[g2][0], bhf[g2][1], bhf[g2][2], bhf[g2][3],
                          sb + OFF_X + boff);
            }
#pragma unroll
            for (int g = 0; g < 4; g++) {
                const uint32_t* bf = &bhf[g >> 1][(g & 1) << 1];
                mma_fp16(acc[g], ah, bf[0], bf[1]);
            }
        }
#pragma unroll
        for (int g = 0; g < 4; g++) {
            int p0 = c0 + g * 8 + ec;
#pragma unroll
            for (int hf = 0; hf < 2; hf++) {
                int l = r0 + er + hf * 8;
                float2 xv = unpackh2(*(uint32_t*)(sm + OFF_X + swz128(l, p0 * 2)));
                *(uint32_t*)&g_y[(size_t)(m0 + l) * D_INNER + h * HEADDIM + p0] =
                    packh2(acc[g][hf * 2 + 0] + Dh * xv.x,
                           acc[g][hf * 2 + 1] + Dh * xv.y);
            }
        }
    }
    __syncthreads();

    // ---- step C: S(p,n) = CX^T @ B -> fp16 g_cs ----
    {
        float acc[4][4];
#pragma unroll
        for (int g = 0; g < 4; g++)
#pragma unroll
            for (int e = 0; e < 4; e++) acc[g][e] = 0.f;
#pragma unroll
        for (int k16 = 0; k16 < 4; k16++) {
            uint32_t ah[4];
            uint32_t aoff =
                swz128(k16 * 16 + ((lane >> 4) & 1) * 8 + (lane & 7),
                       r0 * 2 + (((lane >> 3) & 1) << 4));
            ldsm_x4_t(ah[0], ah[1], ah[2], ah[3], sb + OFF_C + aoff);
            uint32_t bhf[2][4];
#pragma unroll
            for (int g2 = 0; g2 < 2; g2++) {
                uint32_t boff =
                    swz128(k16 * 16 + ((lane >> 3) & 1) * 8 + (lane & 7),
                           (c0 + g2 * 16) * 2 + (((lane >> 4) & 1) << 4));
                ldsm_x4_t(bhf[g2][0], bhf[g2][1], bhf[g2][2], bhf[g2][3],
                          sb + OFF_B + boff);
            }
#pragma unroll
            for (int g = 0; g < 4; g++) {
                const uint32_t* bf = &bhf[g >> 1][(g & 1) << 1];
                mma_fp16(acc[g], ah, bf[0], bf[1]);
            }
        }
        const size_t sbase = (size_t)blk * 4096;
#pragma unroll
        for (int g = 0; g < 4; g++) {
            int n0 = c0 + g * 8 + ec;
#pragma unroll
            for (int hf = 0; hf < 2; hf++) {
                int p = r0 + er + hf * 8;
                *(uint32_t*)&g_cs[sbase + p * 64 + n0] =
                    packh2(acc[g][hf * 2 + 0], acc[g][hf * 2 + 1]);
            }
        }
    }
}

// ------------------------- SSD phase 2: scan (4x par, prefetched, uint2) ----
__global__ void __launch_bounds__(256) ssd_phase2() {
    __shared__ float sT[NCHUNK];
    const int slice = blockIdx.x & 3;
    const int bh    = blockIdx.x >> 2;
    const int tid   = threadIdx.x;
    if (tid < NCHUNK) sT[tid] = g_T[bh * NCHUNK + tid];
    __syncthreads();

    const int off = slice * 1024 + tid * 4;
    const size_t b0 = (size_t)bh * NCHUNK * 4096 + off;
    float s0 = 0.f, s1 = 0.f, s2 = 0.f, s3 = 0.f;
    uint2 nxt = *(const uint2*)&g_cs[b0];
#pragma unroll 4
    for (int c = 0; c < NCHUNK; c++) {
        const size_t base = b0 + (size_t)c * 4096;
        uint2 st;
        st.x = packh2(s0, s1);
        st.y = packh2(s2, s3);
        *(uint2*)&g_ps[base] = st;
        const uint2 cur = nxt;
        if (c + 1 < NCHUNK) nxt = *(const uint2*)&g_cs[base + 4096];
        const float T = sT[c];
        float2 v0 = unpackh2(cur.x);
        float2 v1 = unpackh2(cur.y);
        s0 = s0 * T + v0.x;
        s1 = s1 * T + v0.y;
        s2 = s2 * T + v1.x;
        s3 = s3 * T + v1.y;
    }
}

// ------------------------- SSD phase 3 (fp16 tensor cores) ------------------
__global__ void __launch_bounds__(256) ssd3_tc() {
    __shared__ __align__(16) char t_C[8192];
    __shared__ __align__(16) char t_S[8192];
    __shared__ float s_el[64];
    const uint32_t aC = smem_u32(t_C), aS = smem_u32(t_S);

    const int blk = blockIdx.x;
    const int c   = blk & (NCHUNK - 1);
    const int bh  = blk >> 6;
    const int b = bh >> 5, h = bh & 31;
    const int tid = threadIdx.x, wid = tid >> 5, lane = tid & 31;
    const int r0 = (wid & 3) * 16, c0 = (wid >> 2) * 32;
    const int m0 = b * T_LEN + c * CHUNK;

#pragma unroll
    for (int i = 0; i < 2; i++) {
        int flat = tid + (i << 8);
        int l = flat >> 3, j = flat & 7;
        cp16(aC + swz128(l, j * 16),
             g_xbc + (size_t)(m0 + l) * CONV_DIM + D_INNER + D_STATE + j * 8);
        cp16(aS + swz128(l, j * 16),
             g_ps + (size_t)blk * 4096 + l * 64 + j * 8);
    }
    CP_COMMIT();
    if (tid < 64) s_el[tid] = g_el[(size_t)blk * 64 + tid];
    CP_WAIT(0);
    __syncthreads();

    float acc[4][4];
#pragma unroll
    for (int g = 0; g < 4; g++)
#pragma unroll
        for (int e = 0; e < 4; e++) acc[g][e] = 0.f;
#pragma unroll
    for (int k16 = 0; k16 < 4; k16++) {
        uint32_t ah[4];
        uint32_t aoff = swz128(r0 + (lane & 15), k16 * 32 + ((lane >> 4) << 4));
        ldsm_x4(ah[0], ah[1], ah[2], ah[3], aC + aoff);
        uint32_t bhf[2][4];
#pragma unroll
        for (int g2 = 0; g2 < 2; g2++) {
            uint32_t boff =
                swz128(c0 + g2 * 16 + (lane & 7) + ((lane >> 4) << 3),
                       k16 * 32 + (((lane >> 3) & 1) << 4));
            ldsm_x4(bhf[g2][0], bhf[g2][1], bhf[g2][2], bhf[g2][3], aS + boff);
        }
#pragma unroll
        for (int g = 0; g < 4; g++) {
            const uint32_t* bf = &bhf[g >> 1][(g & 1) << 1];
            mma_fp16(acc[g], ah, bf[0], bf[1]);
        }
    }
    const int er = lane >> 2, ec = (lane & 3) << 1;
#pragma unroll
    for (int g = 0; g < 4; g++) {
        int p0 = c0 + g * 8 + ec;
#pragma unroll
        for (int hf = 0; hf < 2; hf++) {
            int l = r0 + er + hf * 8;
            float el = s_el[l];
            uint32_t* yp =
                (uint32_t*)&g_y[(size_t)(m0 + l) * D_INNER + h * HEADDIM + p0];
            float2 cur = unpackh2(*yp);
            *yp = packh2(cur.x + el * acc[g][hf * 2 + 0],
                         cur.y + el * acc[g][hf * 2 + 1]);
        }
    }
}

// ------------------------- gate + RMSNorm -> fp16 (vectorized) --------------
__global__ void gate_rms_kernel(const float* __restrict__ norm_w,
                                __half* __restrict__ yh) {
    const int m = blockIdx.x;
    const int tid = threadIdx.x;
    const size_t ybase = (size_t)m * D_INNER;
    const size_t zbase = (size_t)m * D_IN_PROJ;
    const int i0 = tid * 8;

    uint4 yraw = *(const uint4*)&g_y[ybase + i0];
    uint4 zraw = *(const uint4*)&g_zxbcdt[zbase + i0];
    float vals[8];
    float ssum = 0.f;
    const uint32_t* yw = (const uint32_t*)&yraw;
    const uint32_t* zw = (const uint32_t*)&zraw;
#pragma unroll
    for (int q = 0; q < 4; q++) {
        float2 yv = unpackh2(yw[q]);
        float2 zv = unpackh2(zw[q]);
        float g0 = yv.x * zv.x / (1.f + expf(-zv.x));
        float g1 = yv.y * zv.y / (1.f + expf(-zv.y));
        vals[q * 2] = g0;
        vals[q * 2 + 1] = g1;
        ssum += g0 * g0 + g1 * g1;
    }
    __shared__ float red[256];
    red[tid] = ssum;
    __syncthreads();
    for (int s = 128; s > 0; s >>= 1) {
        if (tid < s) red[tid] += red[tid + s];
        __syncthreads();
    }
    const float scale = rsqrtf(red[0] / (float)D_INNER + 1e-5f);

    float4 w0 = *(const float4*)&norm_w[i0];
    float4 w1 = *(const float4*)&norm_w[i0 + 4];
    uint4 outw;
    uint32_t* ow = (uint32_t*)&outw;
    ow[0] = packh2(vals[0] * scale * w0.x, vals[1] * scale * w0.y);
    ow[1] = packh2(vals[2] * scale * w0.z, vals[3] * scale * w0.w);
    ow[2] = packh2(vals[4] * scale * w1.x, vals[5] * scale * w1.y);
    ow[3] = packh2(vals[6] * scale * w1.z, vals[7] * scale * w1.w);
    *(uint4*)&yh[ybase + i0] = outw;
}

// ---------------------------------------------------------------------------
extern "C" void kernel_launch(void* const* d_in, const int* in_sizes, int n_in,
                              void* d_out, int out_size) {
    const float* u       = (const float*)d_in[0];
    const float* W_in    = (const float*)d_in[1];
    const float* conv_w  = (const float*)d_in[2];
    const float* conv_b  = (const float*)d_in[3];
    const float* dt_bias = (const float*)d_in[4];
    const float* A_log   = (const float*)d_in[5];
    const float* Dv      = (const float*)d_in[6];
    const float* norm_w  = (const float*)d_in[7];
    const float* W_out   = (const float*)d_in[8];
    float* out = (float*)d_out;

    __half *zx_p, *uh, *wih, *yh, *woh;
    cudaGetSymbolAddress((void**)&zx_p, g_zxbcdt);
    cudaGetSymbolAddress((void**)&uh, g_uh);
    cudaGetSymbolAddress((void**)&wih, g_wih);
    cudaGetSymbolAddress((void**)&yh, g_yh);
    cudaGetSymbolAddress((void**)&woh, g_woh);

    cudaFuncSetAttribute(gemm_mma_kernel<__half>,
                         cudaFuncAttributeMaxDynamicSharedMemorySize, GEMM_SMEM);
    cudaFuncSetAttribute(gemm_mma_kernel<float>,
                         cudaFuncAttributeMaxDynamicSharedMemorySize, GEMM_SMEM);

    {
        int n = M_TOK * D_MODEL;
        cvt_kernel<<<(n / 2 + 255) / 256, 256>>>(u, uh, n);
        n = D_IN_PROJ * D_MODEL;
        cvt_kernel<<<(n / 2 + 255) / 256, 256>>>(W_in, wih, n);
        n = D_MODEL * D_INNER;
        cvt_kernel<<<(n / 2 + 255) / 256, 256>>>(W_out, woh, n);
    }

    gemm_mma_kernel<__half>
        <<<dim3((D_IN_PROJ + 127) / 128, M_TOK / 128), 128, GEMM_SMEM>>>(
            uh, wih, zx_p, M_TOK, D_IN_PROJ, D_MODEL);

    dt_kernel<<<(M_TOK * NHEADS) / 256, 256>>>(dt_bias);
    conv_silu_kernel<<<dim3(CONV_DIM / 128, M_TOK / 64), 256>>>(conv_w, conv_b);

    ssd1_tc<<<NBH * NCHUNK, 256>>>(A_log, Dv);
    ssd_phase2<<<NBH * 4, 256>>>();
    ssd3_tc<<<NBH * NCHUNK, 256>>>();

    gate_rms_kernel<<<M_TOK, 256>>>(norm_w, yh);

    gemm_mma_kernel<float>
        <<<dim3(D_MODEL / 128, M_TOK / 128), 128, GEMM_SMEM>>>(
            yh, woh, out, M_TOK, D_MODEL, D_INNER);
}

// round 14
// speedup vs baseline: 1.3704x; 1.0360x over previous
#include <cuda_runtime.h>
#include <cuda_bf16.h>
#include <cuda_fp16.h>
#include <math.h>
#include <stdint.h>

#define D_MODEL   1024
#define D_STATE   64
#define D_CONV    4
#define D_INNER   2048
#define NHEADS    32
#define HEADDIM   64
#define CHUNK     64
#define CONV_DIM  2176
#define D_IN_PROJ 4256
#define B_SZ      2
#define T_LEN     4096
#define M_TOK     (B_SZ * T_LEN)   // 8192
#define NCHUNK    (T_LEN / CHUNK)  // 64
#define NBH       (B_SZ * NHEADS)  // 64

// ------------------------- scratch (device globals) -------------------------
__device__ __half g_zxbcdt[(size_t)M_TOK * D_IN_PROJ];
__device__ __half g_xbc[(size_t)M_TOK * CONV_DIM];
__device__ float  g_dt[(size_t)M_TOK * NHEADS];
__device__ __half g_y[(size_t)M_TOK * D_INNER];

__device__ __half g_uh[(size_t)M_TOK * D_MODEL];
__device__ __half g_wih[(size_t)D_IN_PROJ * D_MODEL];
__device__ __half g_yh[(size_t)M_TOK * D_INNER];
__device__ __half g_woh[(size_t)D_MODEL * D_INNER];

__device__ __half g_cs[(size_t)NBH * NCHUNK * 64 * 64];
__device__ __half g_ps[(size_t)NBH * NCHUNK * 64 * 64];
__device__ float  g_T[NBH * NCHUNK];
__device__ float  g_el[(size_t)NBH * NCHUNK * CHUNK];

// ------------------------- helpers ------------------------------------------
__device__ __forceinline__ uint32_t smem_u32(const void* p) {
    uint32_t a;
    asm("{ .reg .u64 t; cvta.to.shared.u64 t, %1; cvt.u32.u64 %0, t; }"
        : "=r"(a) : "l"(p));
    return a;
}
__device__ __forceinline__ void ldsm_x4(uint32_t& r0, uint32_t& r1,
                                        uint32_t& r2, uint32_t& r3,
                                        uint32_t addr) {
    asm volatile("ldmatrix.sync.aligned.m8n8.x4.shared.b16 {%0,%1,%2,%3}, [%4];"
                 : "=r"(r0), "=r"(r1), "=r"(r2), "=r"(r3) : "r"(addr));
}
__device__ __forceinline__ void ldsm_x4_t(uint32_t& r0, uint32_t& r1,
                                          uint32_t& r2, uint32_t& r3,
                                          uint32_t addr) {
    asm volatile("ldmatrix.sync.aligned.m8n8.x4.trans.shared.b16 {%0,%1,%2,%3}, [%4];"
                 : "=r"(r0), "=r"(r1), "=r"(r2), "=r"(r3) : "r"(addr));
}
__device__ __forceinline__ void mma_fp16(float* c, const uint32_t* a,
                                         uint32_t b0, uint32_t b1) {
    asm volatile(
        "mma.sync.aligned.m16n8k16.row.col.f32.f16.f16.f32 "
        "{%0,%1,%2,%3}, {%4,%5,%6,%7}, {%8,%9}, {%0,%1,%2,%3};"
        : "+f"(c[0]), "+f"(c[1]), "+f"(c[2]), "+f"(c[3])
        : "r"(a[0]), "r"(a[1]), "r"(a[2]), "r"(a[3]), "r"(b0), "r"(b1));
}
__device__ __forceinline__ void cp16(uint32_t dst, const void* src) {
    asm volatile("cp.async.cg.shared.global [%0], [%1], 16;"
                 :: "r"(dst), "l"(src));
}
__device__ __forceinline__ void cp16z(uint32_t dst, const void* src, int valid) {
    int sz = valid ? 16 : 0;
    asm volatile("cp.async.cg.shared.global [%0], [%1], 16, %2;"
                 :: "r"(dst), "l"(src), "r"(sz));
}
#define CP_COMMIT() asm volatile("cp.async.commit_group;" ::: "memory")
#define CP_WAIT(N)  asm volatile("cp.async.wait_group %0;" :: "n"(N) : "memory")

// 128B-row tile swizzle (rows of 64 halves)
__device__ __forceinline__ uint32_t swz128(int row, int cb) {
    return (uint32_t)(row * 128 + (cb ^ ((row & 7) << 4)));
}
__device__ __forceinline__ uint32_t packh2(float a, float b) {
    __half2 h = __floats2half2_rn(a, b);
    return *(uint32_t*)&h;
}
__device__ __forceinline__ float2 unpackh2(uint32_t w) {
    __half2 h = *(__half2*)&w;
    return make_float2(__half2float(h.x), __half2float(h.y));
}
__device__ __forceinline__ void store2(float* p, float a, float b) {
    *(float2*)p = make_float2(a, b);
}
__device__ __forceinline__ void store2(__half* p, float a, float b) {
    *(__half2*)p = __floats2half2_rn(a, b);
}

// ------------------------- fp32 -> fp16 convert -----------------------------
__global__ void cvt_kernel(const float* __restrict__ src,
                           __half* __restrict__ dst, int n) {
    int i = blockIdx.x * 256 + threadIdx.x;
    if (i * 2 < n) {
        float2 v = *(const float2*)(src + i * 2);
        *(__half2*)(dst + i * 2) = __floats2half2_rn(v.x, v.y);
    }
}

// ------------------------- HMMA GEMM: 128x128x64, 4 warps, 2 CTA/SM ---------
// warp tile 64x64, 3-stage cp.async, fragments pipelined ACROSS slab
// boundaries (next slab's kk=0 ldsm issued under kk=3 mma; barrier at end).
#define GTILE_B  16384                 // 128 x 64 halves
#define GSTAGE_B (2 * GTILE_B)         // 32 KB (A + B)
#define GEMM_SMEM (3 * GSTAGE_B)       // 96 KB
template <typename OT>
__global__ void __launch_bounds__(128, 2) gemm_mma_kernel(
    const __half* __restrict__ A, const __half* __restrict__ B,
    OT* __restrict__ C, int M, int N, int K) {
    extern __shared__ char smem[];
    const uint32_t sb = smem_u32(smem);

    const int tid  = threadIdx.x;
    const int wid  = tid >> 5;
    const int lane = tid & 31;
    const int m0 = blockIdx.y << 7;
    const int n0 = blockIdx.x << 7;
    const int wm0 = (wid >> 1) << 6;
    const int wn0 = (wid & 1) << 6;

    float acc[4][8][4];
#pragma unroll
    for (int f = 0; f < 4; f++)
#pragma unroll
        for (int g = 0; g < 8; g++)
#pragma unroll
            for (int e = 0; e < 4; e++) acc[f][g][e] = 0.f;

    const int nk = K >> 6;

    auto load_stage = [&](int kc, int s) {
        const int k0 = kc << 6;
        const uint32_t st = sb + s * GSTAGE_B;
#pragma unroll
        for (int i = 0; i < 8; i++) {
            const int q = tid + (i << 7);
            const int r = q >> 3, j = q & 7;
            cp16(st + swz128(r, j * 16),
                 A + (size_t)(m0 + r) * K + k0 + j * 8);
        }
#pragma unroll
        for (int i = 0; i < 8; i++) {
            const int q = tid + (i << 7);
            const int r = q >> 3, j = q & 7;
            const int v = (n0 + r) < N;
            const size_t o = v ? (size_t)(n0 + r) * K + k0 + j * 8 : 0;
            cp16z(st + GTILE_B + swz128(r, j * 16), B + o, v);
        }
        CP_COMMIT();
    };

    const int a_row = lane & 15;
    const int a_kb  = (lane >> 4) << 4;
    const int b_row = (lane & 7) + ((lane >> 4) << 3);
    const int b_kb  = ((lane >> 3) & 1) << 4;

    uint32_t ah[2][4][4], bh[2][4][4];

    auto ld_frags = [&](int buf, uint32_t sA_, uint32_t sB_, int kb) {
#pragma unroll
        for (int f = 0; f < 4; f++)
            ldsm_x4(ah[buf][f][0], ah[buf][f][1], ah[buf][f][2], ah[buf][f][3],
                    sA_ + swz128(wm0 + f * 16 + a_row, kb + a_kb));
#pragma unroll
        for (int g2 = 0; g2 < 4; g2++)
            ldsm_x4(bh[buf][g2][0], bh[buf][g2][1], bh[buf][g2][2],
                    bh[buf][g2][3],
                    sB_ + swz128(wn0 + g2 * 16 + b_row, kb + b_kb));
    };
    auto mma_all = [&](int buf) {
#pragma unroll
        for (int f = 0; f < 4; f++)
#pragma unroll
            for (int g = 0; g < 8; g++) {
                const uint32_t* bf = &bh[buf][g >> 1][(g & 1) << 1];
                mma_fp16(acc[f][g], ah[buf][f], bf[0], bf[1]);
            }
    };

    load_stage(0, 0);
    if (nk > 1) load_stage(1, 1); else CP_COMMIT();
    CP_WAIT(1);
    __syncthreads();
    ld_frags(0, sb, sb + GTILE_B, 0);   // prime slab 0, kk=0

    int s_cur = 0;
    for (int kc = 0; kc < nk; kc++) {
        int s_nx = (s_cur == 2) ? 0 : s_cur + 1;
        int s_n2 = (s_nx == 2) ? 0 : s_nx + 1;
        if (kc + 2 < nk) load_stage(kc + 2, s_n2);
        else CP_COMMIT();

        const uint32_t sA = sb + s_cur * GSTAGE_B;
        const uint32_t sB = sA + GTILE_B;
        const uint32_t sAn = sb + s_nx * GSTAGE_B;
        const uint32_t sBn = sAn + GTILE_B;

#pragma unroll
        for (int kk = 0; kk < 3; kk++) {
            ld_frags((kk + 1) & 1, sA, sB, (kk + 1) * 32);
            mma_all(kk & 1);
        }
        CP_WAIT(1);                      // slab kc+1 data now resident
        ld_frags(0, sAn, sBn, 0);        // prefetch next slab kk=0 under kk=3
        mma_all(1);                      // kk=3
        __syncthreads();                 // protect stage s_cur before reuse
        s_cur = s_nx;
    }

    const int er = lane >> 2;
    const int ec = (lane & 3) << 1;
#pragma unroll
    for (int f = 0; f < 4; f++) {
        const int row = m0 + wm0 + f * 16 + er;
#pragma unroll
        for (int g = 0; g < 8; g++) {
            const int col = n0 + wn0 + g * 8 + ec;
            if (col < N) {
                store2(&C[(size_t)row * N + col], acc[f][g][0], acc[f][g][1]);
                store2(&C[(size_t)(row + 8) * N + col], acc[f][g][2],
                       acc[f][g][3]);
            }
        }
    }
}

// ------------------------- dt = softplus(raw + bias) ------------------------
__global__ void dt_kernel(const float* __restrict__ dt_bias) {
    const int idx = blockIdx.x * 256 + threadIdx.x;
    const int m = idx >> 5;
    const int h = idx & 31;
    float v = __half2float(
                  g_zxbcdt[(size_t)m * D_IN_PROJ + (D_INNER + CONV_DIM) + h]) +
              dt_bias[h];
    g_dt[idx] = (v > 20.f) ? v : log1pf(expf(v));
}

// ------------------------- tiled depthwise conv + SiLU (vectorized) ---------
__global__ void __launch_bounds__(256) conv_silu_kernel(
    const float* __restrict__ w, const float* __restrict__ bias) {
    __shared__ float sx[67][128];
    const int cb = blockIdx.x;
    const int tb = blockIdx.y;
    const int tid = threadIdx.x;
    const int m0 = tb * 64;
    const int zero_head = ((m0 & (T_LEN - 1)) == 0);

    for (int idx = tid; idx < 67 * 16; idx += 256) {
        const int r = idx >> 4, j = idx & 15;
        float4 z = make_float4(0.f, 0.f, 0.f, 0.f);
        uint4 raw = *(const uint4*)&z;
        if (r >= 3 || !zero_head)
            raw = *(const uint4*)&g_zxbcdt[(size_t)(m0 - 3 + r) * D_IN_PROJ +
                                           D_INNER + cb * 128 + j * 8];
        const uint32_t* hp = (const uint32_t*)&raw;
#pragma unroll
        for (int q = 0; q < 4; q++) {
            float2 v = unpackh2(hp[q]);
            sx[r][j * 8 + q * 2]     = v.x;
            sx[r][j * 8 + q * 2 + 1] = v.y;
        }
    }
    __syncthreads();

    const int ch = tid & 127;
    const int th = (tid >> 7) * 32;
    const int gc = cb * 128 + ch;
    const float w0 = w[gc * 4 + 0], w1 = w[gc * 4 + 1];
    const float w2 = w[gc * 4 + 2], w3 = w[gc * 4 + 3];
    const float bz = bias[gc];
#pragma unroll 8
    for (int i = 0; i < 32; i++) {
        const int t = th + i;
        float acc = bz + w0 * sx[t][ch] + w1 * sx[t + 1][ch] +
                    w2 * sx[t + 2][ch] + w3 * sx[t + 3][ch];
        g_xbc[(size_t)(m0 + t) * CONV_DIM + gc] =
            __float2half_rn(acc / (1.f + expf(-acc)));
    }
}

// ------------------------- SSD phase 1 (fp16 tensor cores) ------------------
#define OFF_X 0
#define OFF_B 8192
#define OFF_C 16384
#define OFF_M 24576
__global__ void __launch_bounds__(256) ssd1_tc(const float* __restrict__ A_log,
                                               const float* __restrict__ Dvec) {
    __shared__ __align__(16) char sm[32768];
    __shared__ float s_cum[64], s_dt[64], s_coef[64];
    const uint32_t sb = smem_u32(sm);

    const int blk = blockIdx.x;
    const int c   = blk & (NCHUNK - 1);
    const int bh  = blk >> 6;
    const int b = bh >> 5, h = bh & 31;
    const int tid = threadIdx.x, wid = tid >> 5, lane = tid & 31;
    const int r0 = (wid & 3) * 16, c0 = (wid >> 2) * 32;
    const int m0 = b * T_LEN + c * CHUNK;
    const float Ahc = -expf(A_log[h]);
    const float Dh  = Dvec[h];

#pragma unroll
    for (int i = 0; i < 6; i++) {
        int flat = tid + (i << 8);
        int t3 = flat >> 9;
        int wt = flat & 511;
        int l = wt >> 3, j = wt & 7;
        int off = (t3 == 0) ? h * HEADDIM : (t3 == 1) ? D_INNER
                                                      : D_INNER + D_STATE;
        cp16(sb + t3 * 8192 + swz128(l, j * 16),
             g_xbc + (size_t)(m0 + l) * CONV_DIM + off + j * 8);
    }
    CP_COMMIT();
    if (tid < 64) s_dt[tid] = g_dt[(size_t)(m0 + tid) * NHEADS + h];
    CP_WAIT(0);
    __syncthreads();
    if (wid == 0) {
        float v0 = Ahc * s_dt[lane * 2], v1 = Ahc * s_dt[lane * 2 + 1];
        float s = v0 + v1;
#pragma unroll
        for (int o = 1; o < 32; o <<= 1) {
            float t = __shfl_up_sync(0xFFFFFFFF, s, o);
            if (lane >= o) s += t;
        }
        float excl = s - (v0 + v1);
        s_cum[lane * 2] = excl + v0;
        s_cum[lane * 2 + 1] = excl + v0 + v1;
    }
    __syncthreads();
    if (tid < 64) {
        s_coef[tid] = s_dt[tid] * __expf(s_cum[63] - s_cum[tid]);
        g_el[(size_t)blk * 64 + tid] = __expf(s_cum[tid]);
    }
    if (tid == 0) g_T[blk] = __expf(s_cum[63]);
    __syncthreads();

    const int er = lane >> 2, ec = (lane & 3) << 1;

    // ---- step A: G = C @ B^T, mask/decay -> M (fp16) ----
    {
        float acc[4][4];
#pragma unroll
        for (int g = 0; g < 4; g++)
#pragma unroll
            for (int e = 0; e < 4; e++) acc[g][e] = 0.f;
#pragma unroll
        for (int k16 = 0; k16 < 4; k16++) {
            uint32_t ah[4];
            uint32_t aoff = swz128(r0 + (lane & 15),
                                   k16 * 32 + ((lane >> 4) << 4));
            ldsm_x4(ah[0], ah[1], ah[2], ah[3], sb + OFF_C + aoff);
            uint32_t bhf[2][4];
#pragma unroll
            for (int g2 = 0; g2 < 2; g2++) {
                uint32_t boff =
                    swz128(c0 + g2 * 16 + (lane & 7) + ((lane >> 4) << 3),
                           k16 * 32 + (((lane >> 3) & 1) << 4));
                ldsm_x4(bhf[g2][0], bhf[g2][1], bhf[g2][2], bhf[g2][3],
                        sb + OFF_B + boff);
            }
#pragma unroll
            for (int g = 0; g < 4; g++) {
                const uint32_t* bf = &bhf[g >> 1][(g & 1) << 1];
                mma_fp16(acc[g], ah, bf[0], bf[1]);
            }
        }
#pragma unroll
        for (int g = 0; g < 4; g++) {
            int s0 = c0 + g * 8 + ec;
            float cs0 = s_cum[s0], cs1 = s_cum[s0 + 1];
            float d0 = s_dt[s0], d1 = s_dt[s0 + 1];
#pragma unroll
            for (int hf = 0; hf < 2; hf++) {
                int l = r0 + er + hf * 8;
                float cl = s_cum[l];
                float v0 = (s0     <= l) ? acc[g][hf * 2 + 0] * __expf(cl - cs0) * d0 : 0.f;
                float v1 = (s0 + 1 <= l) ? acc[g][hf * 2 + 1] * __expf(cl - cs1) * d1 : 0.f;
                *(uint32_t*)(sm + OFF_M + swz128(l, s0 * 2)) = packh2(v0, v1);
            }
        }
    }
    __syncthreads();

    // ---- CX = coef(l) * x (overwrites C tile) ----
#pragma unroll
    for (int i = 0; i < 8; i++) {
        int flat = tid + (i << 8);
        int l = flat >> 5, q2 = flat & 31;
        uint32_t so = swz128(l, q2 * 4);
        float2 v = unpackh2(*(uint32_t*)(sm + OFF_X + so));
        float cf = s_coef[l];
        *(uint32_t*)(sm + OFF_C + so) = packh2(v.x * cf, v.y * cf);
    }

    // ---- step B: Y = M @ x (+ D skip) -> fp16 g_y ----
    {
        float acc[4][4];
#pragma unroll
        for (int g = 0; g < 4; g++)
#pragma unroll
            for (int e = 0; e < 4; e++) acc[g][e] = 0.f;
#pragma unroll
        for (int k16 = 0; k16 < 4; k16++) {
            uint32_t ah[4];
            uint32_t aoff = swz128(r0 + (lane & 15),
                                   k16 * 32 + ((lane >> 4) << 4));
            ldsm_x4(ah[0], ah[1], ah[2], ah[3], sb + OFF_M + aoff);
            uint32_t bhf[2][4];
#pragma unroll
            for (int g2 = 0; g2 < 2; g2++) {
                uint32_t boff =
                    swz128(k16 * 16 + ((lane >> 3) & 1) * 8 + (lane & 7),
                           (c0 + g2 * 16) * 2 + (((lane >> 4) & 1) << 4));
                ldsm_x4_t(bhf[g2][0], bhf[g2][1], bhf[g2][2], bhf[g2][3],
                          sb + OFF_X + boff);
            }
#pragma unroll
            for (int g = 0; g < 4; g++) {
                const uint32_t* bf = &bhf[g >> 1][(g & 1) << 1];
                mma_fp16(acc[g], ah, bf[0], bf[1]);
            }
        }
#pragma unroll
        for (int g = 0; g < 4; g++) {
            int p0 = c0 + g * 8 + ec;
#pragma unroll
            for (int hf = 0; hf < 2; hf++) {
                int l = r0 + er + hf * 8;
                float2 xv = unpackh2(*(uint32_t*)(sm + OFF_X + swz128(l, p0 * 2)));
                *(uint32_t*)&g_y[(size_t)(m0 + l) * D_INNER + h * HEADDIM + p0] =
                    packh2(acc[g][hf * 2 + 0] + Dh * xv.x,
                           acc[g][hf * 2 + 1] + Dh * xv.y);
            }
        }
    }
    __syncthreads();

    // ---- step C: S(p,n) = CX^T @ B -> fp16 g_cs ----
    {
        float acc[4][4];
#pragma unroll
        for (int g = 0; g < 4; g++)
#pragma unroll
            for (int e = 0; e < 4; e++) acc[g][e] = 0.f;
#pragma unroll
        for (int k16 = 0; k16 < 4; k16++) {
            uint32_t ah[4];
            uint32_t aoff =
                swz128(k16 * 16 + ((lane >> 4) & 1) * 8 + (lane & 7),
                       r0 * 2 + (((lane >> 3) & 1) << 4));
            ldsm_x4_t(ah[0], ah[1], ah[2], ah[3], sb + OFF_C + aoff);
            uint32_t bhf[2][4];
#pragma unroll
            for (int g2 = 0; g2 < 2; g2++) {
                uint32_t boff =
                    swz128(k16 * 16 + ((lane >> 3) & 1) * 8 + (lane & 7),
                           (c0 + g2 * 16) * 2 + (((lane >> 4) & 1) << 4));
                ldsm_x4_t(bhf[g2][0], bhf[g2][1], bhf[g2][2], bhf[g2][3],
                          sb + OFF_B + boff);
            }
#pragma unroll
            for (int g = 0; g < 4; g++) {
                const uint32_t* bf = &bhf[g >> 1][(g & 1) << 1];
                mma_fp16(acc[g], ah, bf[0], bf[1]);
            }
        }
        const size_t sbase = (size_t)blk * 4096;
#pragma unroll
        for (int g = 0; g < 4; g++) {
            int n0 = c0 + g * 8 + ec;
#pragma unroll
            for (int hf = 0; hf < 2; hf++) {
                int p = r0 + er + hf * 8;
                *(uint32_t*)&g_cs[sbase + p * 64 + n0] =
                    packh2(acc[g][hf * 2 + 0], acc[g][hf * 2 + 1]);
            }
        }
    }
}

// ------------------------- SSD phase 2: scan (4x par, prefetched, uint2) ----
__global__ void __launch_bounds__(256) ssd_phase2() {
    __shared__ float sT[NCHUNK];
    const int slice = blockIdx.x & 3;
    const int bh    = blockIdx.x >> 2;
    const int tid   = threadIdx.x;
    if (tid < NCHUNK) sT[tid] = g_T[bh * NCHUNK + tid];
    __syncthreads();

    const int off = slice * 1024 + tid * 4;
    const size_t b0 = (size_t)bh * NCHUNK * 4096 + off;
    float s0 = 0.f, s1 = 0.f, s2 = 0.f, s3 = 0.f;
    uint2 nxt = *(const uint2*)&g_cs[b0];
#pragma unroll 4
    for (int c = 0; c < NCHUNK; c++) {
        const size_t base = b0 + (size_t)c * 4096;
        uint2 st;
        st.x = packh2(s0, s1);
        st.y = packh2(s2, s3);
        *(uint2*)&g_ps[base] = st;
        const uint2 cur = nxt;
        if (c + 1 < NCHUNK) nxt = *(const uint2*)&g_cs[base + 4096];
        const float T = sT[c];
        float2 v0 = unpackh2(cur.x);
        float2 v1 = unpackh2(cur.y);
        s0 = s0 * T + v0.x;
        s1 = s1 * T + v0.y;
        s2 = s2 * T + v1.x;
        s3 = s3 * T + v1.y;
    }
}

// ------------------------- SSD phase 3 (fp16 tensor cores) ------------------
__global__ void __launch_bounds__(256) ssd3_tc() {
    __shared__ __align__(16) char t_C[8192];
    __shared__ __align__(16) char t_S[8192];
    __shared__ float s_el[64];
    const uint32_t aC = smem_u32(t_C), aS = smem_u32(t_S);

    const int blk = blockIdx.x;
    const int c   = blk & (NCHUNK - 1);
    const int bh  = blk >> 6;
    const int b = bh >> 5, h = bh & 31;
    const int tid = threadIdx.x, wid = tid >> 5, lane = tid & 31;
    const int r0 = (wid & 3) * 16, c0 = (wid >> 2) * 32;
    const int m0 = b * T_LEN + c * CHUNK;

#pragma unroll
    for (int i = 0; i < 2; i++) {
        int flat = tid + (i << 8);
        int l = flat >> 3, j = flat & 7;
        cp16(aC + swz128(l, j * 16),
             g_xbc + (size_t)(m0 + l) * CONV_DIM + D_INNER + D_STATE + j * 8);
        cp16(aS + swz128(l, j * 16),
             g_ps + (size_t)blk * 4096 + l * 64 + j * 8);
    }
    CP_COMMIT();
    if (tid < 64) s_el[tid] = g_el[(size_t)blk * 64 + tid];
    CP_WAIT(0);
    __syncthreads();

    float acc[4][4];
#pragma unroll
    for (int g = 0; g < 4; g++)
#pragma unroll
        for (int e = 0; e < 4; e++) acc[g][e] = 0.f;
#pragma unroll
    for (int k16 = 0; k16 < 4; k16++) {
        uint32_t ah[4];
        uint32_t aoff = swz128(r0 + (lane & 15), k16 * 32 + ((lane >> 4) << 4));
        ldsm_x4(ah[0], ah[1], ah[2], ah[3], aC + aoff);
        uint32_t bhf[2][4];
#pragma unroll
        for (int g2 = 0; g2 < 2; g2++) {
            uint32_t boff =
                swz128(c0 + g2 * 16 + (lane & 7) + ((lane >> 4) << 3),
                       k16 * 32 + (((lane >> 3) & 1) << 4));
            ldsm_x4(bhf[g2][0], bhf[g2][1], bhf[g2][2], bhf[g2][3], aS + boff);
        }
#pragma unroll
        for (int g = 0; g < 4; g++) {
            const uint32_t* bf = &bhf[g >> 1][(g & 1) << 1];
            mma_fp16(acc[g], ah, bf[0], bf[1]);
        }
    }
    const int er = lane >> 2, ec = (lane & 3) << 1;
#pragma unroll
    for (int g = 0; g < 4; g++) {
        int p0 = c0 + g * 8 + ec;
#pragma unroll
        for (int hf = 0; hf < 2; hf++) {
            int l = r0 + er + hf * 8;
            float el = s_el[l];
            uint32_t* yp =
                (uint32_t*)&g_y[(size_t)(m0 + l) * D_INNER + h * HEADDIM + p0];
            float2 cur = unpackh2(*yp);
            *yp = packh2(cur.x + el * acc[g][hf * 2 + 0],
                         cur.y + el * acc[g][hf * 2 + 1]);
        }
    }
}

// ------------------------- gate + RMSNorm -> fp16 (vectorized) --------------
__global__ void gate_rms_kernel(const float* __restrict__ norm_w,
                                __half* __restrict__ yh) {
    const int m = blockIdx.x;
    const int tid = threadIdx.x;
    const size_t ybase = (size_t)m * D_INNER;
    const size_t zbase = (size_t)m * D_IN_PROJ;
    const int i0 = tid * 8;

    uint4 yraw = *(const uint4*)&g_y[ybase + i0];
    uint4 zraw = *(const uint4*)&g_zxbcdt[zbase + i0];
    float vals[8];
    float ssum = 0.f;
    const uint32_t* yw = (const uint32_t*)&yraw;
    const uint32_t* zw = (const uint32_t*)&zraw;
#pragma unroll
    for (int q = 0; q < 4; q++) {
        float2 yv = unpackh2(yw[q]);
        float2 zv = unpackh2(zw[q]);
        float g0 = yv.x * zv.x / (1.f + expf(-zv.x));
        float g1 = yv.y * zv.y / (1.f + expf(-zv.y));
        vals[q * 2] = g0;
        vals[q * 2 + 1] = g1;
        ssum += g0 * g0 + g1 * g1;
    }
    __shared__ float red[256];
    red[tid] = ssum;
    __syncthreads();
    for (int s = 128; s > 0; s >>= 1) {
        if (tid < s) red[tid] += red[tid + s];
        __syncthreads();
    }
    const float scale = rsqrtf(red[0] / (float)D_INNER + 1e-5f);

    float4 w0 = *(const float4*)&norm_w[i0];
    float4 w1 = *(const float4*)&norm_w[i0 + 4];
    uint4 outw;
    uint32_t* ow = (uint32_t*)&outw;
    ow[0] = packh2(vals[0] * scale * w0.x, vals[1] * scale * w0.y);
    ow[1] = packh2(vals[2] * scale * w0.z, vals[3] * scale * w0.w);
    ow[2] = packh2(vals[4] * scale * w1.x, vals[5] * scale * w1.y);
    ow[3] = packh2(vals[6] * scale * w1.z, vals[7] * scale * w1.w);
    *(uint4*)&yh[ybase + i0] = outw;
}

// ---------------------------------------------------------------------------
extern "C" void kernel_launch(void* const* d_in, const int* in_sizes, int n_in,
                              void* d_out, int out_size) {
    const float* u       = (const float*)d_in[0];
    const float* W_in    = (const float*)d_in[1];
    const float* conv_w  = (const float*)d_in[2];
    const float* conv_b  = (const float*)d_in[3];
    const float* dt_bias = (const float*)d_in[4];
    const float* A_log   = (const float*)d_in[5];
    const float* Dv      = (const float*)d_in[6];
    const float* norm_w  = (const float*)d_in[7];
    const float* W_out   = (const float*)d_in[8];
    float* out = (float*)d_out;

    __half *zx_p, *uh, *wih, *yh, *woh;
    cudaGetSymbolAddress((void**)&zx_p, g_zxbcdt);
    cudaGetSymbolAddress((void**)&uh, g_uh);
    cudaGetSymbolAddress((void**)&wih, g_wih);
    cudaGetSymbolAddress((void**)&yh, g_yh);
    cudaGetSymbolAddress((void**)&woh, g_woh);

    cudaFuncSetAttribute(gemm_mma_kernel<__half>,
                         cudaFuncAttributeMaxDynamicSharedMemorySize, GEMM_SMEM);
    cudaFuncSetAttribute(gemm_mma_kernel<float>,
                         cudaFuncAttributeMaxDynamicSharedMemorySize, GEMM_SMEM);

    {
        int n = M_TOK * D_MODEL;
        cvt_kernel<<<(n / 2 + 255) / 256, 256>>>(u, uh, n);
        n = D_IN_PROJ * D_MODEL;
        cvt_kernel<<<(n / 2 + 255) / 256, 256>>>(W_in, wih, n);
        n = D_MODEL * D_INNER;
        cvt_kernel<<<(n / 2 + 255) / 256, 256>>>(W_out, woh, n);
    }

    gemm_mma_kernel<__half>
        <<<dim3((D_IN_PROJ + 127) / 128, M_TOK / 128), 128, GEMM_SMEM>>>(
            uh, wih, zx_p, M_TOK, D_IN_PROJ, D_MODEL);

    dt_kernel<<<(M_TOK * NHEADS) / 256, 256>>>(dt_bias);
    conv_silu_kernel<<<dim3(CONV_DIM / 128, M_TOK / 64), 256>>>(conv_w, conv_b);

    ssd1_tc<<<NBH * NCHUNK, 256>>>(A_log, Dv);
    ssd_phase2<<<NBH * 4, 256>>>();
    ssd3_tc<<<NBH * NCHUNK, 256>>>();

    gate_rms_kernel<<<M_TOK, 256>>>(norm_w, yh);

    gemm_mma_kernel<float>
        <<<dim3(D_MODEL / 128, M_TOK / 128), 128, GEMM_SMEM>>>(
            yh, woh, out, M_TOK, D_MODEL, D_INNER);
}

// round 15
// speedup vs baseline: 1.3985x; 1.0205x over previous
#include <cuda_runtime.h>
#include <cuda_bf16.h>
#include <cuda_fp16.h>
#include <math.h>
#include <stdint.h>

#define D_MODEL   1024
#define D_STATE   64
#define D_CONV    4
#define D_INNER   2048
#define NHEADS    32
#define HEADDIM   64
#define CHUNK     64
#define CONV_DIM  2176
#define D_IN_PROJ 4256
#define B_SZ      2
#define T_LEN     4096
#define M_TOK     (B_SZ * T_LEN)   // 8192
#define NCHUNK    (T_LEN / CHUNK)  // 64
#define NBH       (B_SZ * NHEADS)  // 64

// ------------------------- scratch (device globals) -------------------------
__device__ __half g_zxbcdt[(size_t)M_TOK * D_IN_PROJ];
__device__ __half g_xbc[(size_t)M_TOK * CONV_DIM];
__device__ float  g_dt[(size_t)M_TOK * NHEADS];
__device__ __half g_y[(size_t)M_TOK * D_INNER];

__device__ __half g_uh[(size_t)M_TOK * D_MODEL];
__device__ __half g_wih[(size_t)D_IN_PROJ * D_MODEL];
__device__ __half g_yh[(size_t)M_TOK * D_INNER];
__device__ __half g_woh[(size_t)D_MODEL * D_INNER];

__device__ __half g_cs[(size_t)NBH * NCHUNK * 64 * 64];
__device__ __half g_ps[(size_t)NBH * NCHUNK * 64 * 64];
__device__ float  g_T[NBH * NCHUNK];
__device__ float  g_el[(size_t)NBH * NCHUNK * CHUNK];

// ------------------------- helpers ------------------------------------------
__device__ __forceinline__ uint32_t smem_u32(const void* p) {
    uint32_t a;
    asm("{ .reg .u64 t; cvta.to.shared.u64 t, %1; cvt.u32.u64 %0, t; }"
        : "=r"(a) : "l"(p));
    return a;
}
__device__ __forceinline__ void ldsm_x4(uint32_t& r0, uint32_t& r1,
                                        uint32_t& r2, uint32_t& r3,
                                        uint32_t addr) {
    asm volatile("ldmatrix.sync.aligned.m8n8.x4.shared.b16 {%0,%1,%2,%3}, [%4];"
                 : "=r"(r0), "=r"(r1), "=r"(r2), "=r"(r3) : "r"(addr));
}
__device__ __forceinline__ void ldsm_x4_t(uint32_t& r0, uint32_t& r1,
                                          uint32_t& r2, uint32_t& r3,
                                          uint32_t addr) {
    asm volatile("ldmatrix.sync.aligned.m8n8.x4.trans.shared.b16 {%0,%1,%2,%3}, [%4];"
                 : "=r"(r0), "=r"(r1), "=r"(r2), "=r"(r3) : "r"(addr));
}
__device__ __forceinline__ void mma_fp16(float* c, const uint32_t* a,
                                         uint32_t b0, uint32_t b1) {
    asm volatile(
        "mma.sync.aligned.m16n8k16.row.col.f32.f16.f16.f32 "
        "{%0,%1,%2,%3}, {%4,%5,%6,%7}, {%8,%9}, {%0,%1,%2,%3};"
        : "+f"(c[0]), "+f"(c[1]), "+f"(c[2]), "+f"(c[3])
        : "r"(a[0]), "r"(a[1]), "r"(a[2]), "r"(a[3]), "r"(b0), "r"(b1));
}
__device__ __forceinline__ void cp16(uint32_t dst, const void* src) {
    asm volatile("cp.async.cg.shared.global [%0], [%1], 16;"
                 :: "r"(dst), "l"(src));
}
__device__ __forceinline__ void cp16z(uint32_t dst, const void* src, int valid) {
    int sz = valid ? 16 : 0;
    asm volatile("cp.async.cg.shared.global [%0], [%1], 16, %2;"
                 :: "r"(dst), "l"(src), "r"(sz));
}
#define CP_COMMIT() asm volatile("cp.async.commit_group;" ::: "memory")
#define CP_WAIT(N)  asm volatile("cp.async.wait_group %0;" :: "n"(N) : "memory")

// 128B-row tile swizzle (rows of 64 halves)
__device__ __forceinline__ uint32_t swz128(int row, int cb) {
    return (uint32_t)(row * 128 + (cb ^ ((row & 7) << 4)));
}
__device__ __forceinline__ uint32_t packh2(float a, float b) {
    __half2 h = __floats2half2_rn(a, b);
    return *(uint32_t*)&h;
}
__device__ __forceinline__ float2 unpackh2(uint32_t w) {
    __half2 h = *(__half2*)&w;
    return make_float2(__half2float(h.x), __half2float(h.y));
}
__device__ __forceinline__ void store2(float* p, float a, float b) {
    *(float2*)p = make_float2(a, b);
}
__device__ __forceinline__ void store2(__half* p, float a, float b) {
    *(__half2*)p = __floats2half2_rn(a, b);
}
__device__ __forceinline__ float fast_sigmoid(float x) {
    return __fdividef(1.f, 1.f + __expf(-x));
}

// ------------------------- fp32 -> fp16 convert -----------------------------
__global__ void cvt_kernel(const float* __restrict__ src,
                           __half* __restrict__ dst, int n) {
    int i = blockIdx.x * 256 + threadIdx.x;
    if (i * 2 < n) {
        float2 v = *(const float2*)(src + i * 2);
        *(__half2*)(dst + i * 2) = __floats2half2_rn(v.x, v.y);
    }
}

// ------------------------- HMMA GEMM: 128x128x64, 4 warps, 2 CTA/SM ---------
#define GTILE_B  16384
#define GSTAGE_B (2 * GTILE_B)
#define GEMM_SMEM (3 * GSTAGE_B)
template <typename OT>
__global__ void __launch_bounds__(128, 2) gemm_mma_kernel(
    const __half* __restrict__ A, const __half* __restrict__ B,
    OT* __restrict__ C, int M, int N, int K) {
    extern __shared__ char smem[];
    const uint32_t sb = smem_u32(smem);

    const int tid  = threadIdx.x;
    const int wid  = tid >> 5;
    const int lane = tid & 31;
    const int m0 = blockIdx.y << 7;
    const int n0 = blockIdx.x << 7;
    const int wm0 = (wid >> 1) << 6;
    const int wn0 = (wid & 1) << 6;

    float acc[4][8][4];
#pragma unroll
    for (int f = 0; f < 4; f++)
#pragma unroll
        for (int g = 0; g < 8; g++)
#pragma unroll
            for (int e = 0; e < 4; e++) acc[f][g][e] = 0.f;

    const int nk = K >> 6;

    auto load_stage = [&](int kc, int s) {
        const int k0 = kc << 6;
        const uint32_t st = sb + s * GSTAGE_B;
#pragma unroll
        for (int i = 0; i < 8; i++) {
            const int q = tid + (i << 7);
            const int r = q >> 3, j = q & 7;
            cp16(st + swz128(r, j * 16),
                 A + (size_t)(m0 + r) * K + k0 + j * 8);
        }
#pragma unroll
        for (int i = 0; i < 8; i++) {
            const int q = tid + (i << 7);
            const int r = q >> 3, j = q & 7;
            const int v = (n0 + r) < N;
            const size_t o = v ? (size_t)(n0 + r) * K + k0 + j * 8 : 0;
            cp16z(st + GTILE_B + swz128(r, j * 16), B + o, v);
        }
        CP_COMMIT();
    };

    const int a_row = lane & 15;
    const int a_kb  = (lane >> 4) << 4;
    const int b_row = (lane & 7) + ((lane >> 4) << 3);
    const int b_kb  = ((lane >> 3) & 1) << 4;

    uint32_t ah[2][4][4], bh[2][4][4];

    auto ld_frags = [&](int buf, uint32_t sA_, uint32_t sB_, int kb) {
#pragma unroll
        for (int f = 0; f < 4; f++)
            ldsm_x4(ah[buf][f][0], ah[buf][f][1], ah[buf][f][2], ah[buf][f][3],
                    sA_ + swz128(wm0 + f * 16 + a_row, kb + a_kb));
#pragma unroll
        for (int g2 = 0; g2 < 4; g2++)
            ldsm_x4(bh[buf][g2][0], bh[buf][g2][1], bh[buf][g2][2],
                    bh[buf][g2][3],
                    sB_ + swz128(wn0 + g2 * 16 + b_row, kb + b_kb));
    };
    auto mma_all = [&](int buf) {
#pragma unroll
        for (int f = 0; f < 4; f++)
#pragma unroll
            for (int g = 0; g < 8; g++) {
                const uint32_t* bf = &bh[buf][g >> 1][(g & 1) << 1];
                mma_fp16(acc[f][g], ah[buf][f], bf[0], bf[1]);
            }
    };

    load_stage(0, 0);
    if (nk > 1) load_stage(1, 1); else CP_COMMIT();
    CP_WAIT(1);
    __syncthreads();
    ld_frags(0, sb, sb + GTILE_B, 0);

    int s_cur = 0;
    for (int kc = 0; kc < nk; kc++) {
        int s_nx = (s_cur == 2) ? 0 : s_cur + 1;
        int s_n2 = (s_nx == 2) ? 0 : s_nx + 1;
        if (kc + 2 < nk) load_stage(kc + 2, s_n2);
        else CP_COMMIT();

        const uint32_t sA = sb + s_cur * GSTAGE_B;
        const uint32_t sB = sA + GTILE_B;
        const uint32_t sAn = sb + s_nx * GSTAGE_B;
        const uint32_t sBn = sAn + GTILE_B;

#pragma unroll
        for (int kk = 0; kk < 3; kk++) {
            ld_frags((kk + 1) & 1, sA, sB, (kk + 1) * 32);
            mma_all(kk & 1);
        }
        CP_WAIT(1);
        ld_frags(0, sAn, sBn, 0);
        mma_all(1);
        __syncthreads();
        s_cur = s_nx;
    }

    const int er = lane >> 2;
    const int ec = (lane & 3) << 1;
#pragma unroll
    for (int f = 0; f < 4; f++) {
        const int row = m0 + wm0 + f * 16 + er;
#pragma unroll
        for (int g = 0; g < 8; g++) {
            const int col = n0 + wn0 + g * 8 + ec;
            if (col < N) {
                store2(&C[(size_t)row * N + col], acc[f][g][0], acc[f][g][1]);
                store2(&C[(size_t)(row + 8) * N + col], acc[f][g][2],
                       acc[f][g][3]);
            }
        }
    }
}

// ------------------------- dt = softplus(raw + bias), fast ------------------
__global__ void dt_kernel(const float* __restrict__ dt_bias) {
    const int idx = blockIdx.x * 256 + threadIdx.x;
    const int m = idx >> 5;
    const int h = idx & 31;
    float v = __half2float(
                  g_zxbcdt[(size_t)m * D_IN_PROJ + (D_INNER + CONV_DIM) + h]) +
              dt_bias[h];
    g_dt[idx] = (v > 15.f) ? v : __logf(1.f + __expf(v));
}

// ------------------------- tiled depthwise conv + fast SiLU -----------------
__global__ void __launch_bounds__(256) conv_silu_kernel(
    const float* __restrict__ w, const float* __restrict__ bias) {
    __shared__ float sx[67][128];
    const int cb = blockIdx.x;
    const int tb = blockIdx.y;
    const int tid = threadIdx.x;
    const int m0 = tb * 64;
    const int zero_head = ((m0 & (T_LEN - 1)) == 0);

    for (int idx = tid; idx < 67 * 16; idx += 256) {
        const int r = idx >> 4, j = idx & 15;
        float4 z = make_float4(0.f, 0.f, 0.f, 0.f);
        uint4 raw = *(const uint4*)&z;
        if (r >= 3 || !zero_head)
            raw = *(const uint4*)&g_zxbcdt[(size_t)(m0 - 3 + r) * D_IN_PROJ +
                                           D_INNER + cb * 128 + j * 8];
        const uint32_t* hp = (const uint32_t*)&raw;
#pragma unroll
        for (int q = 0; q < 4; q++) {
            float2 v = unpackh2(hp[q]);
            sx[r][j * 8 + q * 2]     = v.x;
            sx[r][j * 8 + q * 2 + 1] = v.y;
        }
    }
    __syncthreads();

    const int ch = tid & 127;
    const int th = (tid >> 7) * 32;
    const int gc = cb * 128 + ch;
    const float w0 = w[gc * 4 + 0], w1 = w[gc * 4 + 1];
    const float w2 = w[gc * 4 + 2], w3 = w[gc * 4 + 3];
    const float bz = bias[gc];
#pragma unroll 8
    for (int i = 0; i < 32; i++) {
        const int t = th + i;
        float acc = bz + w0 * sx[t][ch] + w1 * sx[t + 1][ch] +
                    w2 * sx[t + 2][ch] + w3 * sx[t + 3][ch];
        g_xbc[(size_t)(m0 + t) * CONV_DIM + gc] =
            __float2half_rn(acc * fast_sigmoid(acc));
    }
}

// ------------------------- SSD phase 1 (fp16 tensor cores) ------------------
#define OFF_X 0
#define OFF_B 8192
#define OFF_C 16384
#define OFF_M 24576
__global__ void __launch_bounds__(256) ssd1_tc(const float* __restrict__ A_log,
                                               const float* __restrict__ Dvec) {
    __shared__ __align__(16) char sm[32768];
    __shared__ float s_cum[64], s_dt[64], s_coef[64];
    const uint32_t sb = smem_u32(sm);

    const int blk = blockIdx.x;
    const int c   = blk & (NCHUNK - 1);
    const int bh  = blk >> 6;
    const int b = bh >> 5, h = bh & 31;
    const int tid = threadIdx.x, wid = tid >> 5, lane = tid & 31;
    const int r0 = (wid & 3) * 16, c0 = (wid >> 2) * 32;
    const int m0 = b * T_LEN + c * CHUNK;
    const float Ahc = -expf(A_log[h]);
    const float Dh  = Dvec[h];

#pragma unroll
    for (int i = 0; i < 6; i++) {
        int flat = tid + (i << 8);
        int t3 = flat >> 9;
        int wt = flat & 511;
        int l = wt >> 3, j = wt & 7;
        int off = (t3 == 0) ? h * HEADDIM : (t3 == 1) ? D_INNER
                                                      : D_INNER + D_STATE;
        cp16(sb + t3 * 8192 + swz128(l, j * 16),
             g_xbc + (size_t)(m0 + l) * CONV_DIM + off + j * 8);
    }
    CP_COMMIT();
    if (tid < 64) s_dt[tid] = g_dt[(size_t)(m0 + tid) * NHEADS + h];
    CP_WAIT(0);
    __syncthreads();
    if (wid == 0) {
        float v0 = Ahc * s_dt[lane * 2], v1 = Ahc * s_dt[lane * 2 + 1];
        float s = v0 + v1;
#pragma unroll
        for (int o = 1; o < 32; o <<= 1) {
            float t = __shfl_up_sync(0xFFFFFFFF, s, o);
            if (lane >= o) s += t;
        }
        float excl = s - (v0 + v1);
        s_cum[lane * 2] = excl + v0;
        s_cum[lane * 2 + 1] = excl + v0 + v1;
    }
    __syncthreads();
    if (tid < 64) {
        s_coef[tid] = s_dt[tid] * __expf(s_cum[63] - s_cum[tid]);
        g_el[(size_t)blk * 64 + tid] = __expf(s_cum[tid]);
    }
    if (tid == 0) g_T[blk] = __expf(s_cum[63]);
    __syncthreads();

    const int er = lane >> 2, ec = (lane & 3) << 1;

    // ---- step A: G = C @ B^T, mask/decay -> M (fp16) ----
    {
        float acc[4][4];
#pragma unroll
        for (int g = 0; g < 4; g++)
#pragma unroll
            for (int e = 0; e < 4; e++) acc[g][e] = 0.f;
#pragma unroll
        for (int k16 = 0; k16 < 4; k16++) {
            uint32_t ah[4];
            uint32_t aoff = swz128(r0 + (lane & 15),
                                   k16 * 32 + ((lane >> 4) << 4));
            ldsm_x4(ah[0], ah[1], ah[2], ah[3], sb + OFF_C + aoff);
            uint32_t bhf[2][4];
#pragma unroll
            for (int g2 = 0; g2 < 2; g2++) {
                uint32_t boff =
                    swz128(c0 + g2 * 16 + (lane & 7) + ((lane >> 4) << 3),
                           k16 * 32 + (((lane >> 3) & 1) << 4));
                ldsm_x4(bhf[g2][0], bhf[g2][1], bhf[g2][2], bhf[g2][3],
                        sb + OFF_B + boff);
            }
#pragma unroll
            for (int g = 0; g < 4; g++) {
                const uint32_t* bf = &bhf[g >> 1][(g & 1) << 1];
                mma_fp16(acc[g], ah, bf[0], bf[1]);
            }
        }
#pragma unroll
        for (int g = 0; g < 4; g++) {
            int s0 = c0 + g * 8 + ec;
            float cs0 = s_cum[s0], cs1 = s_cum[s0 + 1];
            float d0 = s_dt[s0], d1 = s_dt[s0 + 1];
#pragma unroll
            for (int hf = 0; hf < 2; hf++) {
                int l = r0 + er + hf * 8;
                float cl = s_cum[l];
                float v0 = (s0     <= l) ? acc[g][hf * 2 + 0] * __expf(cl - cs0) * d0 : 0.f;
                float v1 = (s0 + 1 <= l) ? acc[g][hf * 2 + 1] * __expf(cl - cs1) * d1 : 0.f;
                *(uint32_t*)(sm + OFF_M + swz128(l, s0 * 2)) = packh2(v0, v1);
            }
        }
    }
    __syncthreads();

    // ---- CX = coef(l) * x (overwrites C tile) ----
#pragma unroll
    for (int i = 0; i < 8; i++) {
        int flat = tid + (i << 8);
        int l = flat >> 5, q2 = flat & 31;
        uint32_t so = swz128(l, q2 * 4);
        float2 v = unpackh2(*(uint32_t*)(sm + OFF_X + so));
        float cf = s_coef[l];
        *(uint32_t*)(sm + OFF_C + so) = packh2(v.x * cf, v.y * cf);
    }

    // ---- step B: Y = M @ x (+ D skip) -> fp16 g_y ----
    {
        float acc[4][4];
#pragma unroll
        for (int g = 0; g < 4; g++)
#pragma unroll
            for (int e = 0; e < 4; e++) acc[g][e] = 0.f;
#pragma unroll
        for (int k16 = 0; k16 < 4; k16++) {
            uint32_t ah[4];
            uint32_t aoff = swz128(r0 + (lane & 15),
                                   k16 * 32 + ((lane >> 4) << 4));
            ldsm_x4(ah[0], ah[1], ah[2], ah[3], sb + OFF_M + aoff);
            uint32_t bhf[2][4];
#pragma unroll
            for (int g2 = 0; g2 < 2; g2++) {
                uint32_t boff =
                    swz128(k16 * 16 + ((lane >> 3) & 1) * 8 + (lane & 7),
                           (c0 + g2 * 16) * 2 + (((lane >> 4) & 1) << 4));
                ldsm_x4_t(bhf[g2][0], bhf[g2][1], bhf[g2][2], bhf[g2][3],
                          sb + OFF_X + boff);
            }
#pragma unroll
            for (int g = 0; g < 4; g++) {
                const uint32_t* bf = &bhf[g >> 1][(g & 1) << 1];
                mma_fp16(acc[g], ah, bf[0], bf[1]);
            }
        }
#pragma unroll
        for (int g = 0; g < 4; g++) {
            int p0 = c0 + g * 8 + ec;
#pragma unroll
            for (int hf = 0; hf < 2; hf++) {
                int l = r0 + er + hf * 8;
                float2 xv = unpackh2(*(uint32_t*)(sm + OFF_X + swz128(l, p0 * 2)));
                *(uint32_t*)&g_y[(size_t)(m0 + l) * D_INNER + h * HEADDIM + p0] =
                    packh2(acc[g][hf * 2 + 0] + Dh * xv.x,
                           acc[g][hf * 2 + 1] + Dh * xv.y);
            }
        }
    }
    __syncthreads();

    // ---- step C: S(p,n) = CX^T @ B -> fp16 g_cs ----
    {
        float acc[4][4];
#pragma unroll
        for (int g = 0; g < 4; g++)
#pragma unroll
            for (int e = 0; e < 4; e++) acc[g][e] = 0.f;
#pragma unroll
        for (int k16 = 0; k16 < 4; k16++) {
            uint32_t ah[4];
            uint32_t aoff =
                swz128(k16 * 16 + ((lane >> 4) & 1) * 8 + (lane & 7),
                       r0 * 2 + (((lane >> 3) & 1) << 4));
            ldsm_x4_t(ah[0], ah[1], ah[2], ah[3], sb + OFF_C + aoff);
            uint32_t bhf[2][4];
#pragma unroll
            for (int g2 = 0; g2 < 2; g2++) {
                uint32_t boff =
                    swz128(k16 * 16 + ((lane >> 3) & 1) * 8 + (lane & 7),
                           (c0 + g2 * 16) * 2 + (((lane >> 4) & 1) << 4));
                ldsm_x4_t(bhf[g2][0], bhf[g2][1], bhf[g2][2], bhf[g2][3],
                          sb + OFF_B + boff);
            }
#pragma unroll
            for (int g = 0; g < 4; g++) {
                const uint32_t* bf = &bhf[g >> 1][(g & 1) << 1];
                mma_fp16(acc[g], ah, bf[0], bf[1]);
            }
        }
        const size_t sbase = (size_t)blk * 4096;
#pragma unroll
        for (int g = 0; g < 4; g++) {
            int n0 = c0 + g * 8 + ec;
#pragma unroll
            for (int hf = 0; hf < 2; hf++) {
                int p = r0 + er + hf * 8;
                *(uint32_t*)&g_cs[sbase + p * 64 + n0] =
                    packh2(acc[g][hf * 2 + 0], acc[g][hf * 2 + 1]);
            }
        }
    }
}

// ------------------------- SSD phase 2: scan (4x par, prefetched, uint2) ----
__global__ void __launch_bounds__(256) ssd_phase2() {
    __shared__ float sT[NCHUNK];
    const int slice = blockIdx.x & 3;
    const int bh    = blockIdx.x >> 2;
    const int tid   = threadIdx.x;
    if (tid < NCHUNK) sT[tid] = g_T[bh * NCHUNK + tid];
    __syncthreads();

    const int off = slice * 1024 + tid * 4;
    const size_t b0 = (size_t)bh * NCHUNK * 4096 + off;
    float s0 = 0.f, s1 = 0.f, s2 = 0.f, s3 = 0.f;
    uint2 nxt = *(const uint2*)&g_cs[b0];
#pragma unroll 4
    for (int c = 0; c < NCHUNK; c++) {
        const size_t base = b0 + (size_t)c * 4096;
        uint2 st;
        st.x = packh2(s0, s1);
        st.y = packh2(s2, s3);
        *(uint2*)&g_ps[base] = st;
        const uint2 cur = nxt;
        if (c + 1 < NCHUNK) nxt = *(const uint2*)&g_cs[base + 4096];
        const float T = sT[c];
        float2 v0 = unpackh2(cur.x);
        float2 v1 = unpackh2(cur.y);
        s0 = s0 * T + v0.x;
        s1 = s1 * T + v0.y;
        s2 = s2 * T + v1.x;
        s3 = s3 * T + v1.y;
    }
}

// ------------------------- SSD phase 3 (fp16 tensor cores) ------------------
__global__ void __launch_bounds__(256) ssd3_tc() {
    __shared__ __align__(16) char t_C[8192];
    __shared__ __align__(16) char t_S[8192];
    __shared__ float s_el[64];
    const uint32_t aC = smem_u32(t_C), aS = smem_u32(t_S);

    const int blk = blockIdx.x;
    const int c   = blk & (NCHUNK - 1);
    const int bh  = blk >> 6;
    const int b = bh >> 5, h = bh & 31;
    const int tid = threadIdx.x, wid = tid >> 5, lane = tid & 31;
    const int r0 = (wid & 3) * 16, c0 = (wid >> 2) * 32;
    const int m0 = b * T_LEN + c * CHUNK;

#pragma unroll
    for (int i = 0; i < 2; i++) {
        int flat = tid + (i << 8);
        int l = flat >> 3, j = flat & 7;
        cp16(aC + swz128(l, j * 16),
             g_xbc + (size_t)(m0 + l) * CONV_DIM + D_INNER + D_STATE + j * 8);
        cp16(aS + swz128(l, j * 16),
             g_ps + (size_t)blk * 4096 + l * 64 + j * 8);
    }
    CP_COMMIT();
    if (tid < 64) s_el[tid] = g_el[(size_t)blk * 64 + tid];
    CP_WAIT(0);
    __syncthreads();

    float acc[4][4];
#pragma unroll
    for (int g = 0; g < 4; g++)
#pragma unroll
        for (int e = 0; e < 4; e++) acc[g][e] = 0.f;
#pragma unroll
    for (int k16 = 0; k16 < 4; k16++) {
        uint32_t ah[4];
        uint32_t aoff = swz128(r0 + (lane & 15), k16 * 32 + ((lane >> 4) << 4));
        ldsm_x4(ah[0], ah[1], ah[2], ah[3], aC + aoff);
        uint32_t bhf[2][4];
#pragma unroll
        for (int g2 = 0; g2 < 2; g2++) {
            uint32_t boff =
                swz128(c0 + g2 * 16 + (lane & 7) + ((lane >> 4) << 3),
                       k16 * 32 + (((lane >> 3) & 1) << 4));
            ldsm_x4(bhf[g2][0], bhf[g2][1], bhf[g2][2], bhf[g2][3], aS + boff);
        }
#pragma unroll
        for (int g = 0; g < 4; g++) {
            const uint32_t* bf = &bhf[g >> 1][(g & 1) << 1];
            mma_fp16(acc[g], ah, bf[0], bf[1]);
        }
    }
    const int er = lane >> 2, ec = (lane & 3) << 1;
#pragma unroll
    for (int g = 0; g < 4; g++) {
        int p0 = c0 + g * 8 + ec;
#pragma unroll
        for (int hf = 0; hf < 2; hf++) {
            int l = r0 + er + hf * 8;
            float el = s_el[l];
            uint32_t* yp =
                (uint32_t*)&g_y[(size_t)(m0 + l) * D_INNER + h * HEADDIM + p0];
            float2 cur = unpackh2(*yp);
            *yp = packh2(cur.x + el * acc[g][hf * 2 + 0],
                         cur.y + el * acc[g][hf * 2 + 1]);
        }
    }
}

// ------------------------- gate + RMSNorm -> fp16 (fast, shfl-reduce) -------
__global__ void gate_rms_kernel(const float* __restrict__ norm_w,
                                __half* __restrict__ yh) {
    const int m = blockIdx.x;
    const int tid = threadIdx.x;
    const int lane = tid & 31, wid = tid >> 5;
    const size_t ybase = (size_t)m * D_INNER;
    const size_t zbase = (size_t)m * D_IN_PROJ;
    const int i0 = tid * 8;

    uint4 yraw = *(const uint4*)&g_y[ybase + i0];
    uint4 zraw = *(const uint4*)&g_zxbcdt[zbase + i0];
    float vals[8];
    float ssum = 0.f;
    const uint32_t* yw = (const uint32_t*)&yraw;
    const uint32_t* zw = (const uint32_t*)&zraw;
#pragma unroll
    for (int q = 0; q < 4; q++) {
        float2 yv = unpackh2(yw[q]);
        float2 zv = unpackh2(zw[q]);
        float g0 = yv.x * zv.x * fast_sigmoid(zv.x);
        float g1 = yv.y * zv.y * fast_sigmoid(zv.y);
        vals[q * 2] = g0;
        vals[q * 2 + 1] = g1;
        ssum += g0 * g0 + g1 * g1;
    }
#pragma unroll
    for (int o = 16; o > 0; o >>= 1)
        ssum += __shfl_xor_sync(0xFFFFFFFF, ssum, o);
    __shared__ float wsum[8];
    if (lane == 0) wsum[wid] = ssum;
    __syncthreads();
    if (wid == 0) {
        float v = (lane < 8) ? wsum[lane] : 0.f;
#pragma unroll
        for (int o = 4; o > 0; o >>= 1)
            v += __shfl_xor_sync(0xFFFFFFFF, v, o);
        if (lane == 0) wsum[0] = v;
    }
    __syncthreads();
    const float scale = rsqrtf(wsum[0] / (float)D_INNER + 1e-5f);

    float4 w0 = *(const float4*)&norm_w[i0];
    float4 w1 = *(const float4*)&norm_w[i0 + 4];
    uint4 outw;
    uint32_t* ow = (uint32_t*)&outw;
    ow[0] = packh2(vals[0] * scale * w0.x, vals[1] * scale * w0.y);
    ow[1] = packh2(vals[2] * scale * w0.z, vals[3] * scale * w0.w);
    ow[2] = packh2(vals[4] * scale * w1.x, vals[5] * scale * w1.y);
    ow[3] = packh2(vals[6] * scale * w1.z, vals[7] * scale * w1.w);
    *(uint4*)&yh[ybase + i0] = outw;
}

// ---------------------------------------------------------------------------
extern "C" void kernel_launch(void* const* d_in, const int* in_sizes, int n_in,
                              void* d_out, int out_size) {
    const float* u       = (const float*)d_in[0];
    const float* W_in    = (const float*)d_in[1];
    const float* conv_w  = (const float*)d_in[2];
    const float* conv_b  = (const float*)d_in[3];
    const float* dt_bias = (const float*)d_in[4];
    const float* A_log   = (const float*)d_in[5];
    const float* Dv      = (const float*)d_in[6];
    const float* norm_w  = (const float*)d_in[7];
    const float* W_out   = (const float*)d_in[8];
    float* out = (float*)d_out;

    __half *zx_p, *uh, *wih, *yh, *woh;
    cudaGetSymbolAddress((void**)&zx_p, g_zxbcdt);
    cudaGetSymbolAddress((void**)&uh, g_uh);
    cudaGetSymbolAddress((void**)&wih, g_wih);
    cudaGetSymbolAddress((void**)&yh, g_yh);
    cudaGetSymbolAddress((void**)&woh, g_woh);

    cudaFuncSetAttribute(gemm_mma_kernel<__half>,
                         cudaFuncAttributeMaxDynamicSharedMemorySize, GEMM_SMEM);
    cudaFuncSetAttribute(gemm_mma_kernel<float>,
                         cudaFuncAttributeMaxDynamicSharedMemorySize, GEMM_SMEM);

    {
        int n = M_TOK * D_MODEL;
        cvt_kernel<<<(n / 2 + 255) / 256, 256>>>(u, uh, n);
        n = D_IN_PROJ * D_MODEL;
        cvt_kernel<<<(n / 2 + 255) / 256, 256>>>(W_in, wih, n);
        n = D_MODEL * D_INNER;
        cvt_kernel<<<(n / 2 + 255) / 256, 256>>>(W_out, woh, n);
    }

    gemm_mma_kernel<__half>
        <<<dim3((D_IN_PROJ + 127) / 128, M_TOK / 128), 128, GEMM_SMEM>>>(
            uh, wih, zx_p, M_TOK, D_IN_PROJ, D_MODEL);

    dt_kernel<<<(M_TOK * NHEADS) / 256, 256>>>(dt_bias);
    conv_silu_kernel<<<dim3(CONV_DIM / 128, M_TOK / 64), 256>>>(conv_w, conv_b);

    ssd1_tc<<<NBH * NCHUNK, 256>>>(A_log, Dv);
    ssd_phase2<<<NBH * 4, 256>>>();
    ssd3_tc<<<NBH * NCHUNK, 256>>>();

    gate_rms_kernel<<<M_TOK, 256>>>(norm_w, yh);

    gemm_mma_kernel<float>
        <<<dim3(D_MODEL / 128, M_TOK / 128), 128, GEMM_SMEM>>>(
            yh, woh, out, M_TOK, D_MODEL, D_INNER);
}

// round 16
// speedup vs baseline: 1.4127x; 1.0102x over previous
#include <cuda_runtime.h>
#include <cuda_bf16.h>
#include <cuda_fp16.h>
#include <math.h>
#include <stdint.h>

#define D_MODEL   1024
#define D_STATE   64
#define D_CONV    4
#define D_INNER   2048
#define NHEADS    32
#define HEADDIM   64
#define CHUNK     64
#define CONV_DIM  2176
#define D_IN_PROJ 4256
#define B_SZ      2
#define T_LEN     4096
#define M_TOK     (B_SZ * T_LEN)   // 8192
#define NCHUNK    (T_LEN / CHUNK)  // 64
#define NBH       (B_SZ * NHEADS)  // 64

// ------------------------- scratch (device globals) -------------------------
__device__ __half g_zxbcdt[(size_t)M_TOK * D_IN_PROJ];
__device__ __half g_xbc[(size_t)M_TOK * CONV_DIM];
__device__ __half g_y[(size_t)M_TOK * D_INNER];

__device__ __half g_uh[(size_t)M_TOK * D_MODEL];
__device__ __half g_wih[(size_t)D_IN_PROJ * D_MODEL];
__device__ __half g_yh[(size_t)M_TOK * D_INNER];
__device__ __half g_woh[(size_t)D_MODEL * D_INNER];

__device__ __half g_cs[(size_t)NBH * NCHUNK * 64 * 64];
__device__ __half g_ps[(size_t)NBH * NCHUNK * 64 * 64];
__device__ float  g_T[NBH * NCHUNK];
__device__ float  g_el[(size_t)NBH * NCHUNK * CHUNK];

// ------------------------- helpers ------------------------------------------
__device__ __forceinline__ uint32_t smem_u32(const void* p) {
    uint32_t a;
    asm("{ .reg .u64 t; cvta.to.shared.u64 t, %1; cvt.u32.u64 %0, t; }"
        : "=r"(a) : "l"(p));
    return a;
}
__device__ __forceinline__ void ldsm_x4(uint32_t& r0, uint32_t& r1,
                                        uint32_t& r2, uint32_t& r3,
                                        uint32_t addr) {
    asm volatile("ldmatrix.sync.aligned.m8n8.x4.shared.b16 {%0,%1,%2,%3}, [%4];"
                 : "=r"(r0), "=r"(r1), "=r"(r2), "=r"(r3) : "r"(addr));
}
__device__ __forceinline__ void ldsm_x4_t(uint32_t& r0, uint32_t& r1,
                                          uint32_t& r2, uint32_t& r3,
                                          uint32_t addr) {
    asm volatile("ldmatrix.sync.aligned.m8n8.x4.trans.shared.b16 {%0,%1,%2,%3}, [%4];"
                 : "=r"(r0), "=r"(r1), "=r"(r2), "=r"(r3) : "r"(addr));
}
__device__ __forceinline__ void mma_fp16(float* c, const uint32_t* a,
                                         uint32_t b0, uint32_t b1) {
    asm volatile(
        "mma.sync.aligned.m16n8k16.row.col.f32.f16.f16.f32 "
        "{%0,%1,%2,%3}, {%4,%5,%6,%7}, {%8,%9}, {%0,%1,%2,%3};"
        : "+f"(c[0]), "+f"(c[1]), "+f"(c[2]), "+f"(c[3])
        : "r"(a[0]), "r"(a[1]), "r"(a[2]), "r"(a[3]), "r"(b0), "r"(b1));
}
__device__ __forceinline__ void cp16(uint32_t dst, const void* src) {
    asm volatile("cp.async.cg.shared.global [%0], [%1], 16;"
                 :: "r"(dst), "l"(src));
}
__device__ __forceinline__ void cp16z(uint32_t dst, const void* src, int valid) {
    int sz = valid ? 16 : 0;
    asm volatile("cp.async.cg.shared.global [%0], [%1], 16, %2;"
                 :: "r"(dst), "l"(src), "r"(sz));
}
#define CP_COMMIT() asm volatile("cp.async.commit_group;" ::: "memory")
#define CP_WAIT(N)  asm volatile("cp.async.wait_group %0;" :: "n"(N) : "memory")

// 128B-row tile swizzle (rows of 64 halves)
__device__ __forceinline__ uint32_t swz128(int row, int cb) {
    return (uint32_t)(row * 128 + (cb ^ ((row & 7) << 4)));
}
__device__ __forceinline__ uint32_t packh2(float a, float b) {
    __half2 h = __floats2half2_rn(a, b);
    return *(uint32_t*)&h;
}
__device__ __forceinline__ float2 unpackh2(uint32_t w) {
    __half2 h = *(__half2*)&w;
    return make_float2(__half2float(h.x), __half2float(h.y));
}
__device__ __forceinline__ void store2(float* p, float a, float b) {
    *(float2*)p = make_float2(a, b);
}
__device__ __forceinline__ void store2(__half* p, float a, float b) {
    *(__half2*)p = __floats2half2_rn(a, b);
}
__device__ __forceinline__ float fast_sigmoid(float x) {
    return __fdividef(1.f, 1.f + __expf(-x));
}

// ------------------------- fused fp32 -> fp16 convert (3 arrays) ------------
__global__ void cvt3_kernel(const float* __restrict__ s0, __half* __restrict__ d0,
                            int n0,
                            const float* __restrict__ s1, __half* __restrict__ d1,
                            int n1,
                            const float* __restrict__ s2, __half* __restrict__ d2,
                            int n2) {
    int e = (blockIdx.x * 256 + threadIdx.x) * 2;
    const float* s;
    __half* d;
    if (e < n0) {
        s = s0 + e; d = d0 + e;
    } else if (e < n0 + n1) {
        s = s1 + (e - n0); d = d1 + (e - n0);
    } else if (e < n0 + n1 + n2) {
        s = s2 + (e - n0 - n1); d = d2 + (e - n0 - n1);
    } else {
        return;
    }
    float2 v = *(const float2*)s;
    *(__half2*)d = __floats2half2_rn(v.x, v.y);
}

// ------------------------- HMMA GEMM: 128x128x64, 4 warps, 2 CTA/SM ---------
#define GTILE_B  16384
#define GSTAGE_B (2 * GTILE_B)
#define GEMM_SMEM (3 * GSTAGE_B)
template <typename OT>
__global__ void __launch_bounds__(128, 2) gemm_mma_kernel(
    const __half* __restrict__ A, const __half* __restrict__ B,
    OT* __restrict__ C, int M, int N, int K) {
    extern __shared__ char smem[];
    const uint32_t sb = smem_u32(smem);

    const int tid  = threadIdx.x;
    const int wid  = tid >> 5;
    const int lane = tid & 31;
    const int m0 = blockIdx.y << 7;
    const int n0 = blockIdx.x << 7;
    const int wm0 = (wid >> 1) << 6;
    const int wn0 = (wid & 1) << 6;

    float acc[4][8][4];
#pragma unroll
    for (int f = 0; f < 4; f++)
#pragma unroll
        for (int g = 0; g < 8; g++)
#pragma unroll
            for (int e = 0; e < 4; e++) acc[f][g][e] = 0.f;

    const int nk = K >> 6;

    auto load_stage = [&](int kc, int s) {
        const int k0 = kc << 6;
        const uint32_t st = sb + s * GSTAGE_B;
#pragma unroll
        for (int i = 0; i < 8; i++) {
            const int q = tid + (i << 7);
            const int r = q >> 3, j = q & 7;
            cp16(st + swz128(r, j * 16),
                 A + (size_t)(m0 + r) * K + k0 + j * 8);
        }
#pragma unroll
        for (int i = 0; i < 8; i++) {
            const int q = tid + (i << 7);
            const int r = q >> 3, j = q & 7;
            const int v = (n0 + r) < N;
            const size_t o = v ? (size_t)(n0 + r) * K + k0 + j * 8 : 0;
            cp16z(st + GTILE_B + swz128(r, j * 16), B + o, v);
        }
        CP_COMMIT();
    };

    const int a_row = lane & 15;
    const int a_kb  = (lane >> 4) << 4;
    const int b_row = (lane & 7) + ((lane >> 4) << 3);
    const int b_kb  = ((lane >> 3) & 1) << 4;

    uint32_t ah[2][4][4], bh[2][4][4];

    auto ld_frags = [&](int buf, uint32_t sA_, uint32_t sB_, int kb) {
#pragma unroll
        for (int f = 0; f < 4; f++)
            ldsm_x4(ah[buf][f][0], ah[buf][f][1], ah[buf][f][2], ah[buf][f][3],
                    sA_ + swz128(wm0 + f * 16 + a_row, kb + a_kb));
#pragma unroll
        for (int g2 = 0; g2 < 4; g2++)
            ldsm_x4(bh[buf][g2][0], bh[buf][g2][1], bh[buf][g2][2],
                    bh[buf][g2][3],
                    sB_ + swz128(wn0 + g2 * 16 + b_row, kb + b_kb));
    };
    auto mma_all = [&](int buf) {
#pragma unroll
        for (int f = 0; f < 4; f++)
#pragma unroll
            for (int g = 0; g < 8; g++) {
                const uint32_t* bf = &bh[buf][g >> 1][(g & 1) << 1];
                mma_fp16(acc[f][g], ah[buf][f], bf[0], bf[1]);
            }
    };

    load_stage(0, 0);
    if (nk > 1) load_stage(1, 1); else CP_COMMIT();
    CP_WAIT(1);
    __syncthreads();
    ld_frags(0, sb, sb + GTILE_B, 0);

    int s_cur = 0;
    for (int kc = 0; kc < nk; kc++) {
        int s_nx = (s_cur == 2) ? 0 : s_cur + 1;
        int s_n2 = (s_nx == 2) ? 0 : s_nx + 1;
        if (kc + 2 < nk) load_stage(kc + 2, s_n2);
        else CP_COMMIT();

        const uint32_t sA = sb + s_cur * GSTAGE_B;
        const uint32_t sB = sA + GTILE_B;
        const uint32_t sAn = sb + s_nx * GSTAGE_B;
        const uint32_t sBn = sAn + GTILE_B;

#pragma unroll
        for (int kk = 0; kk < 3; kk++) {
            ld_frags((kk + 1) & 1, sA, sB, (kk + 1) * 32);
            mma_all(kk & 1);
        }
        CP_WAIT(1);
        ld_frags(0, sAn, sBn, 0);
        mma_all(1);
        __syncthreads();
        s_cur = s_nx;
    }

    const int er = lane >> 2;
    const int ec = (lane & 3) << 1;
#pragma unroll
    for (int f = 0; f < 4; f++) {
        const int row = m0 + wm0 + f * 16 + er;
#pragma unroll
        for (int g = 0; g < 8; g++) {
            const int col = n0 + wn0 + g * 8 + ec;
            if (col < N) {
                store2(&C[(size_t)row * N + col], acc[f][g][0], acc[f][g][1]);
                store2(&C[(size_t)(row + 8) * N + col], acc[f][g][2],
                       acc[f][g][3]);
            }
        }
    }
}

// ------------------------- tiled depthwise conv + fast SiLU -----------------
__global__ void __launch_bounds__(256) conv_silu_kernel(
    const float* __restrict__ w, const float* __restrict__ bias) {
    __shared__ float sx[67][128];
    const int cb = blockIdx.x;
    const int tb = blockIdx.y;
    const int tid = threadIdx.x;
    const int m0 = tb * 64;
    const int zero_head = ((m0 & (T_LEN - 1)) == 0);

    for (int idx = tid; idx < 67 * 16; idx += 256) {
        const int r = idx >> 4, j = idx & 15;
        float4 z = make_float4(0.f, 0.f, 0.f, 0.f);
        uint4 raw = *(const uint4*)&z;
        if (r >= 3 || !zero_head)
            raw = *(const uint4*)&g_zxbcdt[(size_t)(m0 - 3 + r) * D_IN_PROJ +
                                           D_INNER + cb * 128 + j * 8];
        const uint32_t* hp = (const uint32_t*)&raw;
#pragma unroll
        for (int q = 0; q < 4; q++) {
            float2 v = unpackh2(hp[q]);
            sx[r][j * 8 + q * 2]     = v.x;
            sx[r][j * 8 + q * 2 + 1] = v.y;
        }
    }
    __syncthreads();

    const int ch = tid & 127;
    const int th = (tid >> 7) * 32;
    const int gc = cb * 128 + ch;
    const float w0 = w[gc * 4 + 0], w1 = w[gc * 4 + 1];
    const float w2 = w[gc * 4 + 2], w3 = w[gc * 4 + 3];
    const float bz = bias[gc];
#pragma unroll 8
    for (int i = 0; i < 32; i++) {
        const int t = th + i;
        float acc = bz + w0 * sx[t][ch] + w1 * sx[t + 1][ch] +
                    w2 * sx[t + 2][ch] + w3 * sx[t + 3][ch];
        g_xbc[(size_t)(m0 + t) * CONV_DIM + gc] =
            __float2half_rn(acc * fast_sigmoid(acc));
    }
}

// ------------------------- SSD phase 1 (fp16 tc, inline softplus) -----------
#define OFF_X 0
#define OFF_B 8192
#define OFF_C 16384
#define OFF_M 24576
__global__ void __launch_bounds__(256) ssd1_tc(const float* __restrict__ A_log,
                                               const float* __restrict__ Dvec,
                                               const float* __restrict__ dt_bias) {
    __shared__ __align__(16) char sm[32768];
    __shared__ float s_cum[64], s_dt[64], s_coef[64];
    const uint32_t sb = smem_u32(sm);

    const int blk = blockIdx.x;
    const int c   = blk & (NCHUNK - 1);
    const int bh  = blk >> 6;
    const int b = bh >> 5, h = bh & 31;
    const int tid = threadIdx.x, wid = tid >> 5, lane = tid & 31;
    const int r0 = (wid & 3) * 16, c0 = (wid >> 2) * 32;
    const int m0 = b * T_LEN + c * CHUNK;
    const float Ahc = -expf(A_log[h]);
    const float Dh  = Dvec[h];

#pragma unroll
    for (int i = 0; i < 6; i++) {
        int flat = tid + (i << 8);
        int t3 = flat >> 9;
        int wt = flat & 511;
        int l = wt >> 3, j = wt & 7;
        int off = (t3 == 0) ? h * HEADDIM : (t3 == 1) ? D_INNER
                                                      : D_INNER + D_STATE;
        cp16(sb + t3 * 8192 + swz128(l, j * 16),
             g_xbc + (size_t)(m0 + l) * CONV_DIM + off + j * 8);
    }
    CP_COMMIT();
    if (tid < 64) {
        float v = __half2float(g_zxbcdt[(size_t)(m0 + tid) * D_IN_PROJ +
                                        (D_INNER + CONV_DIM) + h]) +
                  dt_bias[h];
        s_dt[tid] = (v > 15.f) ? v : __logf(1.f + __expf(v));
    }
    CP_WAIT(0);
    __syncthreads();
    if (wid == 0) {
        float v0 = Ahc * s_dt[lane * 2], v1 = Ahc * s_dt[lane * 2 + 1];
        float s = v0 + v1;
#pragma unroll
        for (int o = 1; o < 32; o <<= 1) {
            float t = __shfl_up_sync(0xFFFFFFFF, s, o);
            if (lane >= o) s += t;
        }
        float excl = s - (v0 + v1);
        s_cum[lane * 2] = excl + v0;
        s_cum[lane * 2 + 1] = excl + v0 + v1;
    }
    __syncthreads();
    if (tid < 64) {
        s_coef[tid] = s_dt[tid] * __expf(s_cum[63] - s_cum[tid]);
        g_el[(size_t)blk * 64 + tid] = __expf(s_cum[tid]);
    }
    if (tid == 0) g_T[blk] = __expf(s_cum[63]);
    __syncthreads();

    const int er = lane >> 2, ec = (lane & 3) << 1;

    // ---- step A: G = C @ B^T, mask/decay -> M (fp16) ----
    {
        float acc[4][4];
#pragma unroll
        for (int g = 0; g < 4; g++)
#pragma unroll
            for (int e = 0; e < 4; e++) acc[g][e] = 0.f;
#pragma unroll
        for (int k16 = 0; k16 < 4; k16++) {
            uint32_t ah[4];
            uint32_t aoff = swz128(r0 + (lane & 15),
                                   k16 * 32 + ((lane >> 4) << 4));
            ldsm_x4(ah[0], ah[1], ah[2], ah[3], sb + OFF_C + aoff);
            uint32_t bhf[2][4];
#pragma unroll
            for (int g2 = 0; g2 < 2; g2++) {
                uint32_t boff =
                    swz128(c0 + g2 * 16 + (lane & 7) + ((lane >> 4) << 3),
                           k16 * 32 + (((lane >> 3) & 1) << 4));
                ldsm_x4(bhf[g2][0], bhf[g2][1], bhf[g2][2], bhf[g2][3],
                        sb + OFF_B + boff);
            }
#pragma unroll
            for (int g = 0; g < 4; g++) {
                const uint32_t* bf = &bhf[g >> 1][(g & 1) << 1];
                mma_fp16(acc[g], ah, bf[0], bf[1]);
            }
        }
#pragma unroll
        for (int g = 0; g < 4; g++) {
            int s0 = c0 + g * 8 + ec;
            float cs0 = s_cum[s0], cs1 = s_cum[s0 + 1];
            float d0 = s_dt[s0], d1 = s_dt[s0 + 1];
#pragma unroll
            for (int hf = 0; hf < 2; hf++) {
                int l = r0 + er + hf * 8;
                float cl = s_cum[l];
                float v0 = (s0     <= l) ? acc[g][hf * 2 + 0] * __expf(cl - cs0) * d0 : 0.f;
                float v1 = (s0 + 1 <= l) ? acc[g][hf * 2 + 1] * __expf(cl - cs1) * d1 : 0.f;
                *(uint32_t*)(sm + OFF_M + swz128(l, s0 * 2)) = packh2(v0, v1);
            }
        }
    }
    __syncthreads();

    // ---- CX = coef(l) * x (overwrites C tile) ----
#pragma unroll
    for (int i = 0; i < 8; i++) {
        int flat = tid + (i << 8);
        int l = flat >> 5, q2 = flat & 31;
        uint32_t so = swz128(l, q2 * 4);
        float2 v = unpackh2(*(uint32_t*)(sm + OFF_X + so));
        float cf = s_coef[l];
        *(uint32_t*)(sm + OFF_C + so) = packh2(v.x * cf, v.y * cf);
    }

    // ---- step B: Y = M @ x (+ D skip) -> fp16 g_y ----
    {
        float acc[4][4];
#pragma unroll
        for (int g = 0; g < 4; g++)
#pragma unroll
            for (int e = 0; e < 4; e++) acc[g][e] = 0.f;
#pragma unroll
        for (int k16 = 0; k16 < 4; k16++) {
            uint32_t ah[4];
            uint32_t aoff = swz128(r0 + (lane & 15),
                                   k16 * 32 + ((lane >> 4) << 4));
            ldsm_x4(ah[0], ah[1], ah[2], ah[3], sb + OFF_M + aoff);
            uint32_t bhf[2][4];
#pragma unroll
            for (int g2 = 0; g2 < 2; g2++) {
                uint32_t boff =
                    swz128(k16 * 16 + ((lane >> 3) & 1) * 8 + (lane & 7),
                           (c0 + g2 * 16) * 2 + (((lane >> 4) & 1) << 4));
                ldsm_x4_t(bhf[g2][0], bhf[g2][1], bhf[g2][2], bhf[g2][3],
                          sb + OFF_X + boff);
            }
#pragma unroll
            for (int g = 0; g < 4; g++) {
                const uint32_t* bf = &bhf[g >> 1][(g & 1) << 1];
                mma_fp16(acc[g], ah, bf[0], bf[1]);
            }
        }
#pragma unroll
        for (int g = 0; g < 4; g++) {
            int p0 = c0 + g * 8 + ec;
#pragma unroll
            for (int hf = 0; hf < 2; hf++) {
                int l = r0 + er + hf * 8;
                float2 xv = unpackh2(*(uint32_t*)(sm + OFF_X + swz128(l, p0 * 2)));
                *(uint32_t*)&g_y[(size_t)(m0 + l) * D_INNER + h * HEADDIM + p0] =
                    packh2(acc[g][hf * 2 + 0] + Dh * xv.x,
                           acc[g][hf * 2 + 1] + Dh * xv.y);
            }
        }
    }
    __syncthreads();

    // ---- step C: S(p,n) = CX^T @ B -> fp16 g_cs ----
    {
        float acc[4][4];
#pragma unroll
        for (int g = 0; g < 4; g++)
#pragma unroll
            for (int e = 0; e < 4; e++) acc[g][e] = 0.f;
#pragma unroll
        for (int k16 = 0; k16 < 4; k16++) {
            uint32_t ah[4];
            uint32_t aoff =
                swz128(k16 * 16 + ((lane >> 4) & 1) * 8 + (lane & 7),
                       r0 * 2 + (((lane >> 3) & 1) << 4));
            ldsm_x4_t(ah[0], ah[1], ah[2], ah[3], sb + OFF_C + aoff);
            uint32_t bhf[2][4];
#pragma unroll
            for (int g2 = 0; g2 < 2; g2++) {
                uint32_t boff =
                    swz128(k16 * 16 + ((lane >> 3) & 1) * 8 + (lane & 7),
                           (c0 + g2 * 16) * 2 + (((lane >> 4) & 1) << 4));
                ldsm_x4_t(bhf[g2][0], bhf[g2][1], bhf[g2][2], bhf[g2][3],
                          sb + OFF_B + boff);
            }
#pragma unroll
            for (int g = 0; g < 4; g++) {
                const uint32_t* bf = &bhf[g >> 1][(g & 1) << 1];
                mma_fp16(acc[g], ah, bf[0], bf[1]);
            }
        }
        const size_t sbase = (size_t)blk * 4096;
#pragma unroll
        for (int g = 0; g < 4; g++) {
            int n0 = c0 + g * 8 + ec;
#pragma unroll
            for (int hf = 0; hf < 2; hf++) {
                int p = r0 + er + hf * 8;
                *(uint32_t*)&g_cs[sbase + p * 64 + n0] =
                    packh2(acc[g][hf * 2 + 0], acc[g][hf * 2 + 1]);
            }
        }
    }
}

// ------------------------- SSD phase 2: scan (8x par, prefetched) -----------
__global__ void __launch_bounds__(256) ssd_phase2() {
    __shared__ float sT[NCHUNK];
    const int slice = blockIdx.x & 7;
    const int bh    = blockIdx.x >> 3;
    const int tid   = threadIdx.x;
    if (tid < NCHUNK) sT[tid] = g_T[bh * NCHUNK + tid];
    __syncthreads();

    const int off = slice * 512 + tid * 2;
    const size_t b0 = (size_t)bh * NCHUNK * 4096 + off;
    float s0 = 0.f, s1 = 0.f;
    uint32_t nxt = *(const uint32_t*)&g_cs[b0];
#pragma unroll 4
    for (int c = 0; c < NCHUNK; c++) {
        const size_t base = b0 + (size_t)c * 4096;
        *(uint32_t*)&g_ps[base] = packh2(s0, s1);
        const uint32_t cur = nxt;
        if (c + 1 < NCHUNK) nxt = *(const uint32_t*)&g_cs[base + 4096];
        const float T = sT[c];
        float2 v = unpackh2(cur);
        s0 = s0 * T + v.x;
        s1 = s1 * T + v.y;
    }
}

// ------------------------- SSD phase 3 (fp16 tensor cores) ------------------
__global__ void __launch_bounds__(256) ssd3_tc() {
    __shared__ __align__(16) char t_C[8192];
    __shared__ __align__(16) char t_S[8192];
    __shared__ float s_el[64];
    const uint32_t aC = smem_u32(t_C), aS = smem_u32(t_S);

    const int blk = blockIdx.x;
    const int c   = blk & (NCHUNK - 1);
    const int bh  = blk >> 6;
    const int b = bh >> 5, h = bh & 31;
    const int tid = threadIdx.x, wid = tid >> 5, lane = tid & 31;
    const int r0 = (wid & 3) * 16, c0 = (wid >> 2) * 32;
    const int m0 = b * T_LEN + c * CHUNK;

#pragma unroll
    for (int i = 0; i < 2; i++) {
        int flat = tid + (i << 8);
        int l = flat >> 3, j = flat & 7;
        cp16(aC + swz128(l, j * 16),
             g_xbc + (size_t)(m0 + l) * CONV_DIM + D_INNER + D_STATE + j * 8);
        cp16(aS + swz128(l, j * 16),
             g_ps + (size_t)blk * 4096 + l * 64 + j * 8);
    }
    CP_COMMIT();
    if (tid < 64) s_el[tid] = g_el[(size_t)blk * 64 + tid];
    CP_WAIT(0);
    __syncthreads();

    float acc[4][4];
#pragma unroll
    for (int g = 0; g < 4; g++)
#pragma unroll
        for (int e = 0; e < 4; e++) acc[g][e] = 0.f;
#pragma unroll
    for (int k16 = 0; k16 < 4; k16++) {
        uint32_t ah[4];
        uint32_t aoff = swz128(r0 + (lane & 15), k16 * 32 + ((lane >> 4) << 4));
        ldsm_x4(ah[0], ah[1], ah[2], ah[3], aC + aoff);
        uint32_t bhf[2][4];
#pragma unroll
        for (int g2 = 0; g2 < 2; g2++) {
            uint32_t boff =
                swz128(c0 + g2 * 16 + (lane & 7) + ((lane >> 4) << 3),
                       k16 * 32 + (((lane >> 3) & 1) << 4));
            ldsm_x4(bhf[g2][0], bhf[g2][1], bhf[g2][2], bhf[g2][3], aS + boff);
        }
#pragma unroll
        for (int g = 0; g < 4; g++) {
            const uint32_t* bf = &bhf[g >> 1][(g & 1) << 1];
            mma_fp16(acc[g], ah, bf[0], bf[1]);
        }
    }
    const int er = lane >> 2, ec = (lane & 3) << 1;
#pragma unroll
    for (int g = 0; g < 4; g++) {
        int p0 = c0 + g * 8 + ec;
#pragma unroll
        for (int hf = 0; hf < 2; hf++) {
            int l = r0 + er + hf * 8;
            float el = s_el[l];
            uint32_t* yp =
                (uint32_t*)&g_y[(size_t)(m0 + l) * D_INNER + h * HEADDIM + p0];
            float2 cur = unpackh2(*yp);
            *yp = packh2(cur.x + el * acc[g][hf * 2 + 0],
                         cur.y + el * acc[g][hf * 2 + 1]);
        }
    }
}

// ------------------------- gate + RMSNorm -> fp16 (fast, shfl-reduce) -------
__global__ void gate_rms_kernel(const float* __restrict__ norm_w,
                                __half* __restrict__ yh) {
    const int m = blockIdx.x;
    const int tid = threadIdx.x;
    const int lane = tid & 31, wid = tid >> 5;
    const size_t ybase = (size_t)m * D_INNER;
    const size_t zbase = (size_t)m * D_IN_PROJ;
    const int i0 = tid * 8;

    uint4 yraw = *(const uint4*)&g_y[ybase + i0];
    uint4 zraw = *(const uint4*)&g_zxbcdt[zbase + i0];
    float vals[8];
    float ssum = 0.f;
    const uint32_t* yw = (const uint32_t*)&yraw;
    const uint32_t* zw = (const uint32_t*)&zraw;
#pragma unroll
    for (int q = 0; q < 4; q++) {
        float2 yv = unpackh2(yw[q]);
        float2 zv = unpackh2(zw[q]);
        float g0 = yv.x * zv.x * fast_sigmoid(zv.x);
        float g1 = yv.y * zv.y * fast_sigmoid(zv.y);
        vals[q * 2] = g0;
        vals[q * 2 + 1] = g1;
        ssum += g0 * g0 + g1 * g1;
    }
#pragma unroll
    for (int o = 16; o > 0; o >>= 1)
        ssum += __shfl_xor_sync(0xFFFFFFFF, ssum, o);
    __shared__ float wsum[8];
    if (lane == 0) wsum[wid] = ssum;
    __syncthreads();
    if (wid == 0) {
        float v = (lane < 8) ? wsum[lane] : 0.f;
#pragma unroll
        for (int o = 4; o > 0; o >>= 1)
            v += __shfl_xor_sync(0xFFFFFFFF, v, o);
        if (lane == 0) wsum[0] = v;
    }
    __syncthreads();
    const float scale = rsqrtf(wsum[0] / (float)D_INNER + 1e-5f);

    float4 w0 = *(const float4*)&norm_w[i0];
    float4 w1 = *(const float4*)&norm_w[i0 + 4];
    uint4 outw;
    uint32_t* ow = (uint32_t*)&outw;
    ow[0] = packh2(vals[0] * scale * w0.x, vals[1] * scale * w0.y);
    ow[1] = packh2(vals[2] * scale * w0.z, vals[3] * scale * w0.w);
    ow[2] = packh2(vals[4] * scale * w1.x, vals[5] * scale * w1.y);
    ow[3] = packh2(vals[6] * scale * w1.z, vals[7] * scale * w1.w);
    *(uint4*)&yh[ybase + i0] = outw;
}

// ---------------------------------------------------------------------------
extern "C" void kernel_launch(void* const* d_in, const int* in_sizes, int n_in,
                              void* d_out, int out_size) {
    const float* u       = (const float*)d_in[0];
    const float* W_in    = (const float*)d_in[1];
    const float* conv_w  = (const float*)d_in[2];
    const float* conv_b  = (const float*)d_in[3];
    const float* dt_bias = (const float*)d_in[4];
    const float* A_log   = (const float*)d_in[5];
    const float* Dv      = (const float*)d_in[6];
    const float* norm_w  = (const float*)d_in[7];
    const float* W_out   = (const float*)d_in[8];
    float* out = (float*)d_out;

    __half *zx_p, *uh, *wih, *yh, *woh;
    cudaGetSymbolAddress((void**)&zx_p, g_zxbcdt);
    cudaGetSymbolAddress((void**)&uh, g_uh);
    cudaGetSymbolAddress((void**)&wih, g_wih);
    cudaGetSymbolAddress((void**)&yh, g_yh);
    cudaGetSymbolAddress((void**)&woh, g_woh);

    cudaFuncSetAttribute(gemm_mma_kernel<__half>,
                         cudaFuncAttributeMaxDynamicSharedMemorySize, GEMM_SMEM);
    cudaFuncSetAttribute(gemm_mma_kernel<float>,
                         cudaFuncAttributeMaxDynamicSharedMemorySize, GEMM_SMEM);

    {
        const int n0 = M_TOK * D_MODEL;        // u
        const int n1 = D_IN_PROJ * D_MODEL;    // W_in
        const int n2 = D_MODEL * D_INNER;      // W_out
        const int total2 = (n0 + n1 + n2) / 2;
        cvt3_kernel<<<(total2 + 255) / 256, 256>>>(u, uh, n0, W_in, wih, n1,
                                                   W_out, woh, n2);
    }

    gemm_mma_kernel<__half>
        <<<dim3((D_IN_PROJ + 127) / 128, M_TOK / 128), 128, GEMM_SMEM>>>(
            uh, wih, zx_p, M_TOK, D_IN_PROJ, D_MODEL);

    conv_silu_kernel<<<dim3(CONV_DIM / 128, M_TOK / 64), 256>>>(conv_w, conv_b);

    ssd1_tc<<<NBH * NCHUNK, 256>>>(A_log, Dv, dt_bias);
    ssd_phase2<<<NBH * 8, 256>>>();
    ssd3_tc<<<NBH * NCHUNK, 256>>>();

    gate_rms_kernel<<<M_TOK, 256>>>(norm_w, yh);

    gemm_mma_kernel<float>
        <<<dim3(D_MODEL / 128, M_TOK / 128), 128, GEMM_SMEM>>>(
            yh, woh, out, M_TOK, D_MODEL, D_INNER);
}